// round 1
// baseline (speedup 1.0000x reference)
#include <cuda_runtime.h>
#include <cuda_bf16.h>
#include <cstdint>
#include <cstddef>

// Problem constants: B=8, S=1024, D=512, H=8, qdim=vdim=64, n=H*B=64
// Outputs: out [8,1024,512] then heatmap [64,1024,1024], concatenated in d_out.

// ---------------- scratch (__device__ globals; no allocation allowed) ----------
__device__ float g_q[64ull * 1024 * 64];   // [n][s][d] split-head q
__device__ float g_k[64ull * 1024 * 64];   // [n][t][d]
__device__ float g_v[64ull * 1024 * 64];   // [n][t][d]
__device__ float g_wv[8ull * 1024 * 512];  // [b][s][h*64+v] recombined attn output

// ---------------- packed f32x2 helpers (FFMA2: 2x fp32 issue rate) ------------
__device__ __forceinline__ unsigned long long pack2(float lo, float hi) {
    unsigned long long r;
    asm("mov.b64 %0, {%1,%2};" : "=l"(r) : "f"(lo), "f"(hi));
    return r;
}
__device__ __forceinline__ float2 unpack2(unsigned long long v) {
    float2 f;
    asm("mov.b64 {%0,%1}, %2;" : "=f"(f.x), "=f"(f.y) : "l"(v));
    return f;
}
__device__ __forceinline__ void fma2(unsigned long long& d,
                                     unsigned long long a,
                                     unsigned long long b) {
    asm("fma.rn.f32x2 %0, %1, %2, %0;" : "+l"(d) : "l"(a), "l"(b));
}
__device__ __forceinline__ void mul2(unsigned long long& d, unsigned long long a) {
    asm("mul.rn.f32x2 %0, %0, %1;" : "+l"(d) : "l"(a));
}

// ---------------- GEMM: C[8192,512] = X[8192,512] @ W[512,512] + bias ---------
// osel: 0 -> plain row-major store to outp
//       1/2/3 -> split-head store into g_q/g_k/g_v : out[(h*8+b)][s][d] = C[b*1024+s][h*64+d]
// xsel: 0 -> X = Xin, 1 -> X = g_wv
__global__ __launch_bounds__(256) void gemm512(const float* __restrict__ Xin,
                                               const float* __restrict__ W,
                                               const float* __restrict__ bias,
                                               float* __restrict__ outp,
                                               int xsel, int osel) {
    const float* X = xsel ? g_wv : Xin;
    float* outq = (osel == 1) ? g_q : (osel == 2) ? g_k : (osel == 3) ? g_v : outp;

    __shared__ float As[16][132];  // k-major A tile (padded: STS conflicts ~2-way)
    __shared__ float Bs[16][128];

    const int tid = threadIdx.x;
    const int tx = tid & 15, ty = tid >> 4;
    const int m0 = blockIdx.y << 7, n0 = blockIdx.x << 7;

    unsigned long long acc[8][4];
#pragma unroll
    for (int i = 0; i < 8; i++)
#pragma unroll
        for (int j = 0; j < 4; j++) acc[i][j] = 0ull;

    const int ar = tid >> 1, ac = (tid & 1) << 3;
    const int br = tid >> 4, bc = (tid & 15) << 3;

    for (int k0 = 0; k0 < 512; k0 += 16) {
        __syncthreads();
        float4 av0 = *(const float4*)(X + (size_t)(m0 + ar) * 512 + k0 + ac);
        float4 av1 = *(const float4*)(X + (size_t)(m0 + ar) * 512 + k0 + ac + 4);
        As[ac + 0][ar] = av0.x; As[ac + 1][ar] = av0.y;
        As[ac + 2][ar] = av0.z; As[ac + 3][ar] = av0.w;
        As[ac + 4][ar] = av1.x; As[ac + 5][ar] = av1.y;
        As[ac + 6][ar] = av1.z; As[ac + 7][ar] = av1.w;
        *(float4*)&Bs[br][bc]     = *(const float4*)(W + (size_t)(k0 + br) * 512 + n0 + bc);
        *(float4*)&Bs[br][bc + 4] = *(const float4*)(W + (size_t)(k0 + br) * 512 + n0 + bc + 4);
        __syncthreads();

#pragma unroll 4
        for (int kk = 0; kk < 16; kk++) {
            float4 a0 = *(const float4*)&As[kk][ty << 3];
            float4 a1 = *(const float4*)&As[kk][(ty << 3) + 4];
            ulonglong2 b0 = *(const ulonglong2*)&Bs[kk][tx << 3];
            ulonglong2 b1 = *(const ulonglong2*)&Bs[kk][(tx << 3) + 4];
            float a_[8] = {a0.x, a0.y, a0.z, a0.w, a1.x, a1.y, a1.z, a1.w};
#pragma unroll
            for (int i = 0; i < 8; i++) {
                unsigned long long aa = pack2(a_[i], a_[i]);
                fma2(acc[i][0], aa, b0.x);
                fma2(acc[i][1], aa, b0.y);
                fma2(acc[i][2], aa, b1.x);
                fma2(acc[i][3], aa, b1.y);
            }
        }
    }

#pragma unroll
    for (int i = 0; i < 8; i++) {
        int m = m0 + (ty << 3) + i;
#pragma unroll
        for (int jp = 0; jp < 4; jp++) {
            float2 v = unpack2(acc[i][jp]);
            int c0 = n0 + (tx << 3) + (jp << 1);
            v.x += bias[c0];
            v.y += bias[c0 + 1];
            if (osel) {
                int h = c0 >> 6, d = c0 & 63;
                int bb = m >> 10, s = m & 1023;
                float* o = outq + (((size_t)(h * 8 + bb)) << 16) + ((size_t)s << 6) + d;
                o[0] = v.x;
                o[1] = v.y;
            } else {
                outq[(size_t)m * 512 + c0] = v.x;
                outq[(size_t)m * 512 + c0 + 1] = v.y;
            }
        }
    }
}

// ---------------- fused attention + heatmap -----------------------------------
// grid = (8 row-blocks, 64 n). Each CTA: q rows [r0, r0+128) of head-batch n.
// For each 128-wide t block: S = q @ k^T (raw) -> written to heatmap;
// causal blocks additionally do online softmax + P@V accumulation.
#define AT_SMEM_FLOATS (64 * 132 * 2 + 128 * 64 + 128 * 132)
#define AT_SMEM_BYTES (AT_SMEM_FLOATS * 4)

__global__ __launch_bounds__(256) void attn_kernel(float* __restrict__ heat) {
    extern __shared__ float smx[];
    float* Qt = smx;               // [64][132]  k-major q block
    float* Kt = Qt + 64 * 132;     // [64][132]  k-major k block
    float* Vs = Kt + 64 * 132;     // [128][64]  v block (t-major)
    float* Ps = Vs + 128 * 64;     // [128][132] probs staging (padded)

    const int tid = threadIdx.x, tx = tid & 15, ty = tid >> 4;
    const int rb = blockIdx.x, n = blockIdx.y;
    const int r0 = rb << 7;
    const int h = n >> 3, bb = n & 7;
    const float* qn = g_q + ((size_t)n << 16);
    const float* kn = g_k + ((size_t)n << 16);
    const float* vn = g_v + ((size_t)n << 16);

#pragma unroll
    for (int it = 0; it < 32; it++) {
        int idx = tid + (it << 8);
        int r = idx >> 6, c = idx & 63;
        Qt[c * 132 + r] = qn[((size_t)(r0 + r) << 6) + c];
    }

    float m_i[8], l_i[8];
    unsigned long long o2[8][2];
#pragma unroll
    for (int i = 0; i < 8; i++) {
        m_i[i] = -1e30f;
        l_i[i] = 0.f;
        o2[i][0] = 0ull;
        o2[i][1] = 0ull;
    }

    for (int tb = 0; tb < 8; tb++) {
        const int t0 = tb << 7;
        __syncthreads();  // previous iteration's smem reads done
#pragma unroll
        for (int it = 0; it < 32; it++) {
            int idx = tid + (it << 8);
            int r = idx >> 6, c = idx & 63;
            Kt[c * 132 + r] = kn[((size_t)(t0 + r) << 6) + c];
            Vs[(r << 6) + c] = vn[((size_t)(t0 + r) << 6) + c];
        }
        __syncthreads();

        // ---- S = Q K^T  (128x128, K=64) ----
        unsigned long long s2[8][4];
#pragma unroll
        for (int i = 0; i < 8; i++) {
            s2[i][0] = 0ull; s2[i][1] = 0ull; s2[i][2] = 0ull; s2[i][3] = 0ull;
        }
#pragma unroll 4
        for (int k = 0; k < 64; k++) {
            float4 a0 = *(const float4*)&Qt[k * 132 + (ty << 3)];
            float4 a1 = *(const float4*)&Qt[k * 132 + (ty << 3) + 4];
            ulonglong2 b0 = *(const ulonglong2*)&Kt[k * 132 + (tx << 3)];
            ulonglong2 b1 = *(const ulonglong2*)&Kt[k * 132 + (tx << 3) + 4];
            float a_[8] = {a0.x, a0.y, a0.z, a0.w, a1.x, a1.y, a1.z, a1.w};
#pragma unroll
            for (int i = 0; i < 8; i++) {
                unsigned long long aa = pack2(a_[i], a_[i]);
                fma2(s2[i][0], aa, b0.x);
                fma2(s2[i][1], aa, b0.y);
                fma2(s2[i][2], aa, b1.x);
                fma2(s2[i][3], aa, b1.y);
            }
        }
        float s[8][8];
#pragma unroll
        for (int i = 0; i < 8; i++) {
            float2 v0 = unpack2(s2[i][0]);
            float2 v1 = unpack2(s2[i][1]);
            float2 v2 = unpack2(s2[i][2]);
            float2 v3 = unpack2(s2[i][3]);
            s[i][0] = v0.x; s[i][1] = v0.y; s[i][2] = v1.x; s[i][3] = v1.y;
            s[i][4] = v2.x; s[i][5] = v2.y; s[i][6] = v3.x; s[i][7] = v3.y;
        }

        // ---- write raw (pre-mask) scores to heatmap ----
        const size_t hb = ((size_t)n << 20) + t0 + (tx << 3);
#pragma unroll
        for (int i = 0; i < 8; i++) {
            int rr = r0 + (ty << 3) + i;
            *(float4*)&heat[hb + ((size_t)rr << 10)] =
                make_float4(s[i][0], s[i][1], s[i][2], s[i][3]);
            *(float4*)&heat[hb + ((size_t)rr << 10) + 4] =
                make_float4(s[i][4], s[i][5], s[i][6], s[i][7]);
        }

        // ---- causal online softmax + P@V ----
        if (tb <= rb) {
            const int cbase = t0 + (tx << 3);
#pragma unroll
            for (int i = 0; i < 8; i++) {
                int rr = r0 + (ty << 3) + i;
                float vmax = -1e30f;
#pragma unroll
                for (int j = 0; j < 8; j++)
                    if (cbase + j <= rr) vmax = fmaxf(vmax, s[i][j]);
#pragma unroll
                for (int off = 8; off; off >>= 1)
                    vmax = fmaxf(vmax, __shfl_xor_sync(0xffffffffu, vmax, off));
                float mnew = fmaxf(m_i[i], vmax);
                float scale = __expf(m_i[i] - mnew);
                float rsum = 0.f;
#pragma unroll
                for (int j = 0; j < 8; j++) {
                    float p = (cbase + j <= rr) ? __expf(s[i][j] - mnew) : 0.f;
                    s[i][j] = p;
                    rsum += p;
                }
#pragma unroll
                for (int off = 8; off; off >>= 1)
                    rsum += __shfl_xor_sync(0xffffffffu, rsum, off);
                l_i[i] = l_i[i] * scale + rsum;
                m_i[i] = mnew;
                unsigned long long ss = pack2(scale, scale);
                mul2(o2[i][0], ss);
                mul2(o2[i][1], ss);
                *(float4*)&Ps[((ty << 3) + i) * 132 + (tx << 3)] =
                    make_float4(s[i][0], s[i][1], s[i][2], s[i][3]);
                *(float4*)&Ps[((ty << 3) + i) * 132 + (tx << 3) + 4] =
                    make_float4(s[i][4], s[i][5], s[i][6], s[i][7]);
            }
            __syncthreads();
            // O += P @ V : rows ty*8+i, v-cols tx*4..tx*4+3, contraction t=0..127
#pragma unroll 4
            for (int t = 0; t < 128; t++) {
                ulonglong2 vv = *(const ulonglong2*)&Vs[(t << 6) + (tx << 2)];
#pragma unroll
                for (int i = 0; i < 8; i++) {
                    float p = Ps[((ty << 3) + i) * 132 + t];
                    unsigned long long pp = pack2(p, p);
                    fma2(o2[i][0], pp, vv.x);
                    fma2(o2[i][1], pp, vv.y);
                }
            }
        }
    }

    // ---- normalize and write recombined wv[b][s][h*64+v] ----
#pragma unroll
    for (int i = 0; i < 8; i++) {
        float inv = 1.0f / l_i[i];
        float2 v0 = unpack2(o2[i][0]);
        float2 v1 = unpack2(o2[i][1]);
        int rr = r0 + (ty << 3) + i;
        float4 w = make_float4(v0.x * inv, v0.y * inv, v1.x * inv, v1.y * inv);
        *(float4*)&g_wv[((size_t)(bb << 10) + rr) * 512 + (h << 6) + (tx << 2)] = w;
    }
}

// ---------------- launch ------------------------------------------------------
extern "C" void kernel_launch(void* const* d_in, const int* in_sizes, int n_in,
                              void* d_out, int out_size) {
    const float* x  = (const float*)d_in[0];
    const float* Wq = (const float*)d_in[1];
    const float* bq = (const float*)d_in[2];
    const float* Wk = (const float*)d_in[3];
    const float* bk = (const float*)d_in[4];
    const float* Wv = (const float*)d_in[5];
    const float* bv = (const float*)d_in[6];
    const float* Wo = (const float*)d_in[7];
    const float* bo = (const float*)d_in[8];

    float* out = (float*)d_out;
    float* heat = out + (size_t)8 * 1024 * 512;  // heatmap follows out

    cudaFuncSetAttribute(attn_kernel, cudaFuncAttributeMaxDynamicSharedMemorySize,
                         AT_SMEM_BYTES);

    dim3 gg(4, 64), bt(256);
    gemm512<<<gg, bt>>>(x, Wq, bq, nullptr, 0, 1);        // q  -> g_q (split heads)
    gemm512<<<gg, bt>>>(x, Wk, bk, nullptr, 0, 2);        // k  -> g_k
    gemm512<<<gg, bt>>>(x, Wv, bv, nullptr, 0, 3);        // v  -> g_v
    attn_kernel<<<dim3(8, 64), bt, AT_SMEM_BYTES>>>(heat);
    gemm512<<<gg, bt>>>(nullptr, Wo, bo, out, 1, 0);      // out = wv @ Wo + bo
}

// round 3
// speedup vs baseline: 1.4028x; 1.4028x over previous
#include <cuda_runtime.h>
#include <cuda_bf16.h>
#include <cstdint>
#include <cstddef>

// Problem constants: B=8, S=1024, D=512, H=8, qdim=vdim=64, n=H*B=64
// Outputs: out [8,1024,512] then heatmap [64,1024,1024], concatenated in d_out.

// ---------------- scratch (__device__ globals; no allocation allowed) ----------
__device__ float g_q[64ull * 1024 * 64];   // [n][s][d] split-head q (fp32)
__device__ float g_k[64ull * 1024 * 64];   // [n][t][d]
__device__ float g_v[64ull * 1024 * 64];   // [n][t][d]
__device__ __nv_bfloat16 g_xhi[8192ull * 512];   // split-bf16 of x
__device__ __nv_bfloat16 g_xlo[8192ull * 512];
__device__ __nv_bfloat16 g_wvhi[8192ull * 512];  // split-bf16 of attn output
__device__ __nv_bfloat16 g_wvlo[8192ull * 512];
__device__ __nv_bfloat16 g_wth[4][512 * 512];    // transposed weights [n][k], hi
__device__ __nv_bfloat16 g_wtl[4][512 * 512];    // lo

// ---------------- packed f32x2 helpers (attn SIMT path) -----------------------
__device__ __forceinline__ unsigned long long pack2(float lo, float hi) {
    unsigned long long r;
    asm("mov.b64 %0, {%1,%2};" : "=l"(r) : "f"(lo), "f"(hi));
    return r;
}
__device__ __forceinline__ float2 unpack2(unsigned long long v) {
    float2 f;
    asm("mov.b64 {%0,%1}, %2;" : "=f"(f.x), "=f"(f.y) : "l"(v));
    return f;
}
__device__ __forceinline__ void fma2(unsigned long long& d,
                                     unsigned long long a,
                                     unsigned long long b) {
    asm("fma.rn.f32x2 %0, %1, %2, %0;" : "+l"(d) : "l"(a), "l"(b));
}
__device__ __forceinline__ void mul2(unsigned long long& d, unsigned long long a) {
    asm("mul.rn.f32x2 %0, %0, %1;" : "+l"(d) : "l"(a));
}

// ---------------- warp mma helper ---------------------------------------------
__device__ __forceinline__ void mma16816(float* c, const uint32_t* a, const uint32_t* b) {
    asm volatile(
        "mma.sync.aligned.m16n8k16.row.col.f32.bf16.bf16.f32 "
        "{%0,%1,%2,%3}, {%4,%5,%6,%7}, {%8,%9}, {%0,%1,%2,%3};"
        : "+f"(c[0]), "+f"(c[1]), "+f"(c[2]), "+f"(c[3])
        : "r"(a[0]), "r"(a[1]), "r"(a[2]), "r"(a[3]), "r"(b[0]), "r"(b[1]));
}

// ---------------- conversion kernels ------------------------------------------
__global__ __launch_bounds__(256) void conv_x(const float* __restrict__ X) {
    size_t i = ((size_t)blockIdx.x * 256 + threadIdx.x) * 4;
    float4 v = *(const float4*)(X + i);
    __nv_bfloat16 h0 = __float2bfloat16_rn(v.x);
    __nv_bfloat16 h1 = __float2bfloat16_rn(v.y);
    __nv_bfloat16 h2 = __float2bfloat16_rn(v.z);
    __nv_bfloat16 h3 = __float2bfloat16_rn(v.w);
    __nv_bfloat16 l0 = __float2bfloat16_rn(v.x - __bfloat162float(h0));
    __nv_bfloat16 l1 = __float2bfloat16_rn(v.y - __bfloat162float(h1));
    __nv_bfloat16 l2 = __float2bfloat16_rn(v.z - __bfloat162float(h2));
    __nv_bfloat16 l3 = __float2bfloat16_rn(v.w - __bfloat162float(h3));
    *(__nv_bfloat162*)(g_xhi + i) = __nv_bfloat162(h0, h1);
    *(__nv_bfloat162*)(g_xhi + i + 2) = __nv_bfloat162(h2, h3);
    *(__nv_bfloat162*)(g_xlo + i) = __nv_bfloat162(l0, l1);
    *(__nv_bfloat162*)(g_xlo + i + 2) = __nv_bfloat162(l2, l3);
}

// W [512 (k), 512 (n)] fp32 -> Wt [n][k] bf16 hi/lo
__global__ void conv_wt(const float* __restrict__ W, int widx) {
    __shared__ float t[32][33];
    int k = blockIdx.y * 32 + threadIdx.y;
    int n = blockIdx.x * 32 + threadIdx.x;
    t[threadIdx.y][threadIdx.x] = W[(size_t)k * 512 + n];
    __syncthreads();
    int n2 = blockIdx.x * 32 + threadIdx.y;
    int k2 = blockIdx.y * 32 + threadIdx.x;
    float v = t[threadIdx.x][threadIdx.y];
    __nv_bfloat16 h = __float2bfloat16_rn(v);
    g_wth[widx][(size_t)n2 * 512 + k2] = h;
    g_wtl[widx][(size_t)n2 * 512 + k2] = __float2bfloat16_rn(v - __bfloat162float(h));
}

// ---------------- HMMA split-bf16 GEMM ----------------------------------------
// C[8192,512] = A[8192,512] @ Wt^T + bias ; A,Wt in split bf16 (hi/lo).
// CTA tile 128x128, 8 warps (2x4), warp tile 64x32, K chunks of 32.
// mode: 0 -> row-major to outp; 1/2/3 -> split-head to g_q/g_k/g_v.
#define TPAD 40  // bf16 per smem row (conflict-free fragment loads)

__device__ __forceinline__ void tg_ldg(uint4* v,
                                       const __nv_bfloat16* __restrict__ Ah,
                                       const __nv_bfloat16* __restrict__ Al,
                                       const __nv_bfloat16* __restrict__ Bh,
                                       const __nv_bfloat16* __restrict__ Bl,
                                       int m0, int n0, int k0, int tid) {
    const int row = tid >> 1, half = tid & 1;
    const uint4* p;
    p = (const uint4*)(Ah + (size_t)(m0 + row) * 512 + k0 + half * 16);
    v[0] = p[0]; v[1] = p[1];
    p = (const uint4*)(Al + (size_t)(m0 + row) * 512 + k0 + half * 16);
    v[2] = p[0]; v[3] = p[1];
    p = (const uint4*)(Bh + (size_t)(n0 + row) * 512 + k0 + half * 16);
    v[4] = p[0]; v[5] = p[1];
    p = (const uint4*)(Bl + (size_t)(n0 + row) * 512 + k0 + half * 16);
    v[6] = p[0]; v[7] = p[1];
}

__device__ __forceinline__ void tg_sts(const uint4* v, __nv_bfloat16* sAh,
                                       __nv_bfloat16* sAl, __nv_bfloat16* sBh,
                                       __nv_bfloat16* sBl, int tid) {
    const int row = tid >> 1, half = tid & 1;
    uint4* d;
    d = (uint4*)(sAh + row * TPAD + half * 16); d[0] = v[0]; d[1] = v[1];
    d = (uint4*)(sAl + row * TPAD + half * 16); d[0] = v[2]; d[1] = v[3];
    d = (uint4*)(sBh + row * TPAD + half * 16); d[0] = v[4]; d[1] = v[5];
    d = (uint4*)(sBl + row * TPAD + half * 16); d[0] = v[6]; d[1] = v[7];
}

__global__ __launch_bounds__(256) void tgemm(int asel, int widx,
                                             const float* __restrict__ bias,
                                             float* __restrict__ outp, int mode) {
    __shared__ __nv_bfloat16 sAh[128 * TPAD], sAl[128 * TPAD];
    __shared__ __nv_bfloat16 sBh[128 * TPAD], sBl[128 * TPAD];

    const int tid = threadIdx.x;
    const int wid = tid >> 5, lane = tid & 31;
    const int gid = lane >> 2, tig = lane & 3;
    const int wm0 = (wid >> 2) << 6;   // 0 or 64
    const int wn0 = (wid & 3) << 5;    // 0,32,64,96
    const int n0 = blockIdx.x << 7, m0 = blockIdx.y << 7;

    const __nv_bfloat16* Ah = asel ? g_wvhi : g_xhi;
    const __nv_bfloat16* Al = asel ? g_wvlo : g_xlo;
    const __nv_bfloat16* Bh = g_wth[widx];
    const __nv_bfloat16* Bl = g_wtl[widx];

    float acc[4][4][4];
#pragma unroll
    for (int i = 0; i < 4; i++)
#pragma unroll
        for (int j = 0; j < 4; j++)
#pragma unroll
            for (int e = 0; e < 4; e++) acc[i][j][e] = 0.f;

    uint4 v[8];
    tg_ldg(v, Ah, Al, Bh, Bl, m0, n0, 0, tid);

    for (int c = 0; c < 16; c++) {
        __syncthreads();
        tg_sts(v, sAh, sAl, sBh, sBl, tid);
        __syncthreads();
        if (c < 15) tg_ldg(v, Ah, Al, Bh, Bl, m0, n0, (c + 1) << 5, tid);

#pragma unroll
        for (int ks = 0; ks < 32; ks += 16) {
            uint32_t ah[4][4], al[4][4], bh[4][2], bl[4][2];
            const int cb = ks + (tig << 1);
#pragma unroll
            for (int i = 0; i < 4; i++) {
                const int r = wm0 + (i << 4) + gid;
                ah[i][0] = *(const uint32_t*)&sAh[r * TPAD + cb];
                ah[i][1] = *(const uint32_t*)&sAh[(r + 8) * TPAD + cb];
                ah[i][2] = *(const uint32_t*)&sAh[r * TPAD + cb + 8];
                ah[i][3] = *(const uint32_t*)&sAh[(r + 8) * TPAD + cb + 8];
                al[i][0] = *(const uint32_t*)&sAl[r * TPAD + cb];
                al[i][1] = *(const uint32_t*)&sAl[(r + 8) * TPAD + cb];
                al[i][2] = *(const uint32_t*)&sAl[r * TPAD + cb + 8];
                al[i][3] = *(const uint32_t*)&sAl[(r + 8) * TPAD + cb + 8];
            }
#pragma unroll
            for (int j = 0; j < 4; j++) {
                const int n = wn0 + (j << 3) + gid;
                bh[j][0] = *(const uint32_t*)&sBh[n * TPAD + cb];
                bh[j][1] = *(const uint32_t*)&sBh[n * TPAD + cb + 8];
                bl[j][0] = *(const uint32_t*)&sBl[n * TPAD + cb];
                bl[j][1] = *(const uint32_t*)&sBl[n * TPAD + cb + 8];
            }
#pragma unroll
            for (int i = 0; i < 4; i++)
#pragma unroll
                for (int j = 0; j < 4; j++) {
                    mma16816(acc[i][j], ah[i], bh[j]);
                    mma16816(acc[i][j], ah[i], bl[j]);
                    mma16816(acc[i][j], al[i], bh[j]);
                }
        }
    }

    // epilogue
    float* qbase = (mode == 1) ? g_q : (mode == 2) ? g_k : g_v;
#pragma unroll
    for (int i = 0; i < 4; i++) {
        const int r = m0 + wm0 + (i << 4) + gid;
#pragma unroll
        for (int j = 0; j < 4; j++) {
            const int col = n0 + wn0 + (j << 3) + (tig << 1);
            const float b0 = bias[col], b1 = bias[col + 1];
            float2 w0 = make_float2(acc[i][j][0] + b0, acc[i][j][1] + b1);
            float2 w1 = make_float2(acc[i][j][2] + b0, acc[i][j][3] + b1);
            if (mode == 0) {
                *(float2*)(outp + (size_t)r * 512 + col) = w0;
                *(float2*)(outp + (size_t)(r + 8) * 512 + col) = w1;
            } else {
                const int h = col >> 6, d = col & 63;
                const int bb = r >> 10, s = r & 1023;
                float* p0 = qbase + (((size_t)(h * 8 + bb)) << 16) + ((size_t)s << 6) + d;
                *(float2*)p0 = w0;
                *(float2*)(p0 + (8ull << 6)) = w1;  // s+8 within same 1024 block
            }
        }
    }
}

// ---------------- fused attention + heatmap (SIMT) ----------------------------
#define AT_SMEM_FLOATS (64 * 132 * 2 + 128 * 64 + 128 * 132)
#define AT_SMEM_BYTES (AT_SMEM_FLOATS * 4)

__global__ __launch_bounds__(256) void attn_kernel(float* __restrict__ heat) {
    extern __shared__ float smx[];
    float* Qt = smx;               // [64][132]  k-major q block
    float* Kt = Qt + 64 * 132;     // [64][132]  k-major k block
    float* Vs = Kt + 64 * 132;     // [128][64]  v block (t-major)
    float* Ps = Vs + 128 * 64;     // [128][132] probs staging (padded)

    const int tid = threadIdx.x, tx = tid & 15, ty = tid >> 4;
    const int rb = blockIdx.x, n = blockIdx.y;
    const int r0 = rb << 7;
    const int h = n >> 3, bb = n & 7;
    const float* qn = g_q + ((size_t)n << 16);
    const float* kn = g_k + ((size_t)n << 16);
    const float* vn = g_v + ((size_t)n << 16);

#pragma unroll
    for (int it = 0; it < 32; it++) {
        int idx = tid + (it << 8);
        int r = idx >> 6, c = idx & 63;
        Qt[c * 132 + r] = qn[((size_t)(r0 + r) << 6) + c];
    }

    float m_i[8], l_i[8];
    unsigned long long o2[8][2];
#pragma unroll
    for (int i = 0; i < 8; i++) {
        m_i[i] = -1e30f;
        l_i[i] = 0.f;
        o2[i][0] = 0ull;
        o2[i][1] = 0ull;
    }

    for (int tb = 0; tb < 8; tb++) {
        const int t0 = tb << 7;
        __syncthreads();
#pragma unroll
        for (int it = 0; it < 32; it++) {
            int idx = tid + (it << 8);
            int r = idx >> 6, c = idx & 63;
            Kt[c * 132 + r] = kn[((size_t)(t0 + r) << 6) + c];
            Vs[(r << 6) + c] = vn[((size_t)(t0 + r) << 6) + c];
        }
        __syncthreads();

        unsigned long long s2[8][4];
#pragma unroll
        for (int i = 0; i < 8; i++) {
            s2[i][0] = 0ull; s2[i][1] = 0ull; s2[i][2] = 0ull; s2[i][3] = 0ull;
        }
#pragma unroll 4
        for (int k = 0; k < 64; k++) {
            float4 a0 = *(const float4*)&Qt[k * 132 + (ty << 3)];
            float4 a1 = *(const float4*)&Qt[k * 132 + (ty << 3) + 4];
            ulonglong2 b0 = *(const ulonglong2*)&Kt[k * 132 + (tx << 3)];
            ulonglong2 b1 = *(const ulonglong2*)&Kt[k * 132 + (tx << 3) + 4];
            float a_[8] = {a0.x, a0.y, a0.z, a0.w, a1.x, a1.y, a1.z, a1.w};
#pragma unroll
            for (int i = 0; i < 8; i++) {
                unsigned long long aa = pack2(a_[i], a_[i]);
                fma2(s2[i][0], aa, b0.x);
                fma2(s2[i][1], aa, b0.y);
                fma2(s2[i][2], aa, b1.x);
                fma2(s2[i][3], aa, b1.y);
            }
        }
        float s[8][8];
#pragma unroll
        for (int i = 0; i < 8; i++) {
            float2 v0 = unpack2(s2[i][0]);
            float2 v1 = unpack2(s2[i][1]);
            float2 v2 = unpack2(s2[i][2]);
            float2 v3 = unpack2(s2[i][3]);
            s[i][0] = v0.x; s[i][1] = v0.y; s[i][2] = v1.x; s[i][3] = v1.y;
            s[i][4] = v2.x; s[i][5] = v2.y; s[i][6] = v3.x; s[i][7] = v3.y;
        }

        const size_t hb = ((size_t)n << 20) + t0 + (tx << 3);
#pragma unroll
        for (int i = 0; i < 8; i++) {
            int rr = r0 + (ty << 3) + i;
            *(float4*)&heat[hb + ((size_t)rr << 10)] =
                make_float4(s[i][0], s[i][1], s[i][2], s[i][3]);
            *(float4*)&heat[hb + ((size_t)rr << 10) + 4] =
                make_float4(s[i][4], s[i][5], s[i][6], s[i][7]);
        }

        if (tb <= rb) {
            const int cbase = t0 + (tx << 3);
#pragma unroll
            for (int i = 0; i < 8; i++) {
                int rr = r0 + (ty << 3) + i;
                float vmax = -1e30f;
#pragma unroll
                for (int j = 0; j < 8; j++)
                    if (cbase + j <= rr) vmax = fmaxf(vmax, s[i][j]);
#pragma unroll
                for (int off = 8; off; off >>= 1)
                    vmax = fmaxf(vmax, __shfl_xor_sync(0xffffffffu, vmax, off));
                float mnew = fmaxf(m_i[i], vmax);
                float scale = __expf(m_i[i] - mnew);
                float rsum = 0.f;
#pragma unroll
                for (int j = 0; j < 8; j++) {
                    float p = (cbase + j <= rr) ? __expf(s[i][j] - mnew) : 0.f;
                    s[i][j] = p;
                    rsum += p;
                }
#pragma unroll
                for (int off = 8; off; off >>= 1)
                    rsum += __shfl_xor_sync(0xffffffffu, rsum, off);
                l_i[i] = l_i[i] * scale + rsum;
                m_i[i] = mnew;
                unsigned long long ss = pack2(scale, scale);
                mul2(o2[i][0], ss);
                mul2(o2[i][1], ss);
                *(float4*)&Ps[((ty << 3) + i) * 132 + (tx << 3)] =
                    make_float4(s[i][0], s[i][1], s[i][2], s[i][3]);
                *(float4*)&Ps[((ty << 3) + i) * 132 + (tx << 3) + 4] =
                    make_float4(s[i][4], s[i][5], s[i][6], s[i][7]);
            }
            __syncthreads();
#pragma unroll 4
            for (int t = 0; t < 128; t++) {
                ulonglong2 vv = *(const ulonglong2*)&Vs[(t << 6) + (tx << 2)];
#pragma unroll
                for (int i = 0; i < 8; i++) {
                    float p = Ps[((ty << 3) + i) * 132 + t];
                    unsigned long long pp = pack2(p, p);
                    fma2(o2[i][0], pp, vv.x);
                    fma2(o2[i][1], pp, vv.y);
                }
            }
        }
    }

    // normalize and write recombined wv[b][s][h*64+v] as split bf16 hi/lo
#pragma unroll
    for (int i = 0; i < 8; i++) {
        float inv = 1.0f / l_i[i];
        float2 v0 = unpack2(o2[i][0]);
        float2 v1 = unpack2(o2[i][1]);
        int rr = r0 + (ty << 3) + i;
        float w[4] = {v0.x * inv, v0.y * inv, v1.x * inv, v1.y * inv};
        size_t idx = ((size_t)(bb << 10) + rr) * 512 + (h << 6) + (tx << 2);
        __nv_bfloat16 hh[4], ll[4];
#pragma unroll
        for (int j = 0; j < 4; j++) {
            hh[j] = __float2bfloat16_rn(w[j]);
            ll[j] = __float2bfloat16_rn(w[j] - __bfloat162float(hh[j]));
        }
        *(__nv_bfloat162*)(g_wvhi + idx) = __nv_bfloat162(hh[0], hh[1]);
        *(__nv_bfloat162*)(g_wvhi + idx + 2) = __nv_bfloat162(hh[2], hh[3]);
        *(__nv_bfloat162*)(g_wvlo + idx) = __nv_bfloat162(ll[0], ll[1]);
        *(__nv_bfloat162*)(g_wvlo + idx + 2) = __nv_bfloat162(ll[2], ll[3]);
    }
}

// ---------------- launch ------------------------------------------------------
extern "C" void kernel_launch(void* const* d_in, const int* in_sizes, int n_in,
                              void* d_out, int out_size) {
    const float* x  = (const float*)d_in[0];
    const float* Wq = (const float*)d_in[1];
    const float* bq = (const float*)d_in[2];
    const float* Wk = (const float*)d_in[3];
    const float* bk = (const float*)d_in[4];
    const float* Wv = (const float*)d_in[5];
    const float* bv = (const float*)d_in[6];
    const float* Wo = (const float*)d_in[7];
    const float* bo = (const float*)d_in[8];

    float* out = (float*)d_out;
    float* heat = out + (size_t)8 * 1024 * 512;  // heatmap follows out

    cudaFuncSetAttribute(attn_kernel, cudaFuncAttributeMaxDynamicSharedMemorySize,
                         AT_SMEM_BYTES);

    conv_x<<<4096, 256>>>(x);
    dim3 wtb(32, 32), wtg(16, 16);
    conv_wt<<<wtg, wtb>>>(Wq, 0);
    conv_wt<<<wtg, wtb>>>(Wk, 1);
    conv_wt<<<wtg, wtb>>>(Wv, 2);
    conv_wt<<<wtg, wtb>>>(Wo, 3);

    dim3 tg(4, 64);
    tgemm<<<tg, 256>>>(0, 0, bq, nullptr, 1);  // q -> g_q split-head
    tgemm<<<tg, 256>>>(0, 1, bk, nullptr, 2);  // k -> g_k
    tgemm<<<tg, 256>>>(0, 2, bv, nullptr, 3);  // v -> g_v
    attn_kernel<<<dim3(8, 64), 256, AT_SMEM_BYTES>>>(heat);
    tgemm<<<tg, 256>>>(1, 3, bo, out, 0);      // out = wv @ Wo + bo
}

// round 5
// speedup vs baseline: 2.0601x; 1.4686x over previous
#include <cuda_runtime.h>
#include <cuda_bf16.h>
#include <cstdint>
#include <cstddef>

// B=8, S=1024, D=512, H=8, qdim=vdim=64, n=H*B=64
// d_out = out [8,1024,512] ++ heatmap [64,1024,1024]

// ---------------- scratch globals (bf16 pairs stored as u32 words) ------------
__device__ uint32_t g_qhi32[64ull * 1024 * 32], g_qlo32[64ull * 1024 * 32];
__device__ uint32_t g_khi32[64ull * 1024 * 32], g_klo32[64ull * 1024 * 32];
__device__ uint32_t g_vhi32[64ull * 1024 * 32], g_vlo32[64ull * 1024 * 32];
__device__ uint32_t g_wvhi32[8192ull * 256], g_wvlo32[8192ull * 256];
__device__ __nv_bfloat16 g_xhi[8192ull * 512], g_xlo[8192ull * 512];
__device__ __nv_bfloat16 g_wth[4][512 * 512], g_wtl[4][512 * 512];

// ---------------- helpers ------------------------------------------------------
__device__ __forceinline__ void mma16816(float* c, const uint32_t* a, const uint32_t* b) {
    asm volatile(
        "mma.sync.aligned.m16n8k16.row.col.f32.bf16.bf16.f32 "
        "{%0,%1,%2,%3}, {%4,%5,%6,%7}, {%8,%9}, {%0,%1,%2,%3};"
        : "+f"(c[0]), "+f"(c[1]), "+f"(c[2]), "+f"(c[3])
        : "r"(a[0]), "r"(a[1]), "r"(a[2]), "r"(a[3]), "r"(b[0]), "r"(b[1]));
}
__device__ __forceinline__ uint32_t packbf(float lo, float hi) {
    uint32_t r;
    asm("cvt.rn.bf16x2.f32 %0, %1, %2;" : "=r"(r) : "f"(hi), "f"(lo));
    return r;
}
__device__ __forceinline__ void split2(float a, float b, uint32_t& hw, uint32_t& lw) {
    uint32_t h = packbf(a, b);
    __nv_bfloat162 h2 = *reinterpret_cast<__nv_bfloat162*>(&h);
    float ra = a - __low2float(h2);
    float rb = b - __high2float(h2);
    hw = h;
    lw = packbf(ra, rb);
}

// ---------------- conversion kernels ------------------------------------------
__global__ __launch_bounds__(256) void conv_x(const float* __restrict__ X) {
    size_t i = ((size_t)blockIdx.x * 256 + threadIdx.x) * 4;
    float4 v = *(const float4*)(X + i);
    uint32_t h0, l0, h1, l1;
    split2(v.x, v.y, h0, l0);
    split2(v.z, v.w, h1, l1);
    *(uint32_t*)(g_xhi + i) = h0;
    *(uint32_t*)(g_xhi + i + 2) = h1;
    *(uint32_t*)(g_xlo + i) = l0;
    *(uint32_t*)(g_xlo + i + 2) = l1;
}

__global__ void conv_wt(const float* __restrict__ W, int widx) {
    __shared__ float t[32][33];
    int k = blockIdx.y * 32 + threadIdx.y;
    int n = blockIdx.x * 32 + threadIdx.x;
    t[threadIdx.y][threadIdx.x] = W[(size_t)k * 512 + n];
    __syncthreads();
    int n2 = blockIdx.x * 32 + threadIdx.y;
    int k2 = blockIdx.y * 32 + threadIdx.x;
    float v = t[threadIdx.x][threadIdx.y];
    __nv_bfloat16 h = __float2bfloat16_rn(v);
    g_wth[widx][(size_t)n2 * 512 + k2] = h;
    g_wtl[widx][(size_t)n2 * 512 + k2] = __float2bfloat16_rn(v - __bfloat162float(h));
}

// ---------------- HMMA split-bf16 GEMM ----------------------------------------
#define TPAD 40

__device__ __forceinline__ void tg_ldg(uint4* v,
                                       const __nv_bfloat16* __restrict__ Ah,
                                       const __nv_bfloat16* __restrict__ Al,
                                       const __nv_bfloat16* __restrict__ Bh,
                                       const __nv_bfloat16* __restrict__ Bl,
                                       int m0, int n0, int k0, int tid) {
    const int row = tid >> 1, half = tid & 1;
    const uint4* p;
    p = (const uint4*)(Ah + (size_t)(m0 + row) * 512 + k0 + half * 16);
    v[0] = p[0]; v[1] = p[1];
    p = (const uint4*)(Al + (size_t)(m0 + row) * 512 + k0 + half * 16);
    v[2] = p[0]; v[3] = p[1];
    p = (const uint4*)(Bh + (size_t)(n0 + row) * 512 + k0 + half * 16);
    v[4] = p[0]; v[5] = p[1];
    p = (const uint4*)(Bl + (size_t)(n0 + row) * 512 + k0 + half * 16);
    v[6] = p[0]; v[7] = p[1];
}
__device__ __forceinline__ void tg_sts(const uint4* v, __nv_bfloat16* sAh,
                                       __nv_bfloat16* sAl, __nv_bfloat16* sBh,
                                       __nv_bfloat16* sBl, int tid) {
    const int row = tid >> 1, half = tid & 1;
    uint4* d;
    d = (uint4*)(sAh + row * TPAD + half * 16); d[0] = v[0]; d[1] = v[1];
    d = (uint4*)(sAl + row * TPAD + half * 16); d[0] = v[2]; d[1] = v[3];
    d = (uint4*)(sBh + row * TPAD + half * 16); d[0] = v[4]; d[1] = v[5];
    d = (uint4*)(sBl + row * TPAD + half * 16); d[0] = v[6]; d[1] = v[7];
}

__global__ __launch_bounds__(256) void tgemm(int asel, int widx,
                                             const float* __restrict__ bias,
                                             float* __restrict__ outp, int mode) {
    __shared__ __nv_bfloat16 sAh[128 * TPAD], sAl[128 * TPAD];
    __shared__ __nv_bfloat16 sBh[128 * TPAD], sBl[128 * TPAD];

    const int tid = threadIdx.x;
    const int wid = tid >> 5, lane = tid & 31;
    const int gid = lane >> 2, tig = lane & 3;
    const int wm0 = (wid >> 2) << 6;
    const int wn0 = (wid & 3) << 5;
    const int n0 = blockIdx.x << 7, m0 = blockIdx.y << 7;

    const __nv_bfloat16* Ah = asel ? (const __nv_bfloat16*)g_wvhi32 : g_xhi;
    const __nv_bfloat16* Al = asel ? (const __nv_bfloat16*)g_wvlo32 : g_xlo;
    const __nv_bfloat16* Bh = g_wth[widx];
    const __nv_bfloat16* Bl = g_wtl[widx];

    float acc[4][4][4];
#pragma unroll
    for (int i = 0; i < 4; i++)
#pragma unroll
        for (int j = 0; j < 4; j++)
#pragma unroll
            for (int e = 0; e < 4; e++) acc[i][j][e] = 0.f;

    uint4 v[8];
    tg_ldg(v, Ah, Al, Bh, Bl, m0, n0, 0, tid);

    for (int c = 0; c < 16; c++) {
        __syncthreads();
        tg_sts(v, sAh, sAl, sBh, sBl, tid);
        __syncthreads();
        if (c < 15) tg_ldg(v, Ah, Al, Bh, Bl, m0, n0, (c + 1) << 5, tid);

#pragma unroll
        for (int ks = 0; ks < 32; ks += 16) {
            uint32_t ah[4][4], al[4][4], bh[4][2], bl[4][2];
            const int cb = ks + (tig << 1);
#pragma unroll
            for (int i = 0; i < 4; i++) {
                const int r = wm0 + (i << 4) + gid;
                ah[i][0] = *(const uint32_t*)&sAh[r * TPAD + cb];
                ah[i][1] = *(const uint32_t*)&sAh[(r + 8) * TPAD + cb];
                ah[i][2] = *(const uint32_t*)&sAh[r * TPAD + cb + 8];
                ah[i][3] = *(const uint32_t*)&sAh[(r + 8) * TPAD + cb + 8];
                al[i][0] = *(const uint32_t*)&sAl[r * TPAD + cb];
                al[i][1] = *(const uint32_t*)&sAl[(r + 8) * TPAD + cb];
                al[i][2] = *(const uint32_t*)&sAl[r * TPAD + cb + 8];
                al[i][3] = *(const uint32_t*)&sAl[(r + 8) * TPAD + cb + 8];
            }
#pragma unroll
            for (int j = 0; j < 4; j++) {
                const int n = wn0 + (j << 3) + gid;
                bh[j][0] = *(const uint32_t*)&sBh[n * TPAD + cb];
                bh[j][1] = *(const uint32_t*)&sBh[n * TPAD + cb + 8];
                bl[j][0] = *(const uint32_t*)&sBl[n * TPAD + cb];
                bl[j][1] = *(const uint32_t*)&sBl[n * TPAD + cb + 8];
            }
#pragma unroll
            for (int i = 0; i < 4; i++)
#pragma unroll
                for (int j = 0; j < 4; j++) {
                    mma16816(acc[i][j], ah[i], bh[j]);
                    mma16816(acc[i][j], ah[i], bl[j]);
                    mma16816(acc[i][j], al[i], bh[j]);
                }
        }
    }

    uint32_t* qh = (mode == 1) ? g_qhi32 : (mode == 2) ? g_khi32 : g_vhi32;
    uint32_t* ql = (mode == 1) ? g_qlo32 : (mode == 2) ? g_klo32 : g_vlo32;
#pragma unroll
    for (int i = 0; i < 4; i++) {
        const int r = m0 + wm0 + (i << 4) + gid;
#pragma unroll
        for (int j = 0; j < 4; j++) {
            const int col = n0 + wn0 + (j << 3) + (tig << 1);
            const float b0 = bias[col], b1 = bias[col + 1];
            float w00 = acc[i][j][0] + b0, w01 = acc[i][j][1] + b1;
            float w10 = acc[i][j][2] + b0, w11 = acc[i][j][3] + b1;
            if (mode == 0) {
                *(float2*)(outp + (size_t)r * 512 + col) = make_float2(w00, w01);
                *(float2*)(outp + (size_t)(r + 8) * 512 + col) = make_float2(w10, w11);
            } else {
                const int h = col >> 6, d = col & 63;
                const int bb = r >> 10, s = r & 1023;
                size_t w = (((size_t)(h * 8 + bb)) << 15) + ((size_t)s << 5) + (d >> 1);
                uint32_t hw, lw;
                split2(w00, w01, hw, lw);
                qh[w] = hw; ql[w] = lw;
                split2(w10, w11, hw, lw);
                qh[w + 256] = hw; ql[w + 256] = lw;  // row s+8
            }
        }
    }
}

// ---------------- tensorized fused attention + heatmap ------------------------
#define AT_SMEM_BYTES ((4608 * 2 + 4352 * 2) * 4)

__global__ __launch_bounds__(256) void attn_kernel(float* __restrict__ heat) {
    extern __shared__ uint32_t sm[];
    uint32_t* sKh = sm;
    uint32_t* sKl = sm + 4608;
    uint32_t* sVh = sm + 9216;
    uint32_t* sVl = sm + 13568;

    const int tid = threadIdx.x;
    const int wid = tid >> 5, lane = tid & 31;
    const int gid = lane >> 2, tig = lane & 3;
    const int rb = blockIdx.x, n = blockIdx.y;
    const int r0 = rb << 7, wr = wid << 4;
    const int hh = n >> 3, bb = n & 7;
    const uint32_t nbase = n << 15;

#pragma unroll
    for (int i = 0; i < 16; i++) {
        int idx = tid + (i << 8);
        int r = idx >> 5, c = idx & 31;
        sKh[r * 36 + c] = g_qhi32[nbase + ((r0 + r) << 5) + c];
        sKl[r * 36 + c] = g_qlo32[nbase + ((r0 + r) << 5) + c];
    }
    __syncthreads();
    uint32_t qhf[4][4], qlf[4][4];
#pragma unroll
    for (int kc = 0; kc < 4; kc++) {
        int b0 = (wr + gid) * 36 + (kc << 3) + tig;
        int b1 = (wr + gid + 8) * 36 + (kc << 3) + tig;
        qhf[kc][0] = sKh[b0]; qhf[kc][1] = sKh[b1];
        qhf[kc][2] = sKh[b0 + 4]; qhf[kc][3] = sKh[b1 + 4];
        qlf[kc][0] = sKl[b0]; qlf[kc][1] = sKl[b1];
        qlf[kc][2] = sKl[b0 + 4]; qlf[kc][3] = sKl[b1 + 4];
    }

    float m0 = -1e30f, m1 = -1e30f, l0 = 0.f, l1 = 0.f;
    float oacc[8][4];
#pragma unroll
    for (int j = 0; j < 8; j++)
#pragma unroll
        for (int e = 0; e < 4; e++) oacc[j][e] = 0.f;

    const int row0 = r0 + wr + gid, row1 = row0 + 8;

    for (int tb = 0; tb < 8; tb++) {
        const int t0 = tb << 7;
        const bool causal = (tb <= rb);
        __syncthreads();
#pragma unroll
        for (int i = 0; i < 16; i++) {
            int idx = tid + (i << 8);
            int r = idx >> 5, c = idx & 31;
            sKh[r * 36 + c] = g_khi32[nbase + ((t0 + r) << 5) + c];
            sKl[r * 36 + c] = g_klo32[nbase + ((t0 + r) << 5) + c];
        }
        if (causal) {
            const int tp = tid >> 2;
            const int t = tp << 1;
#pragma unroll
            for (int i = 0; i < 8; i++) {
                const int vp = (tid & 3) + (i << 2);
                const int v = vp << 1;
                uint32_t a = g_vhi32[nbase + ((t0 + t) << 5) + vp];
                uint32_t b = g_vhi32[nbase + ((t0 + t + 1) << 5) + vp];
                sVh[v * 68 + tp] = (a & 0xffffu) | (b << 16);
                sVh[(v + 1) * 68 + tp] = (a >> 16) | (b & 0xffff0000u);
                a = g_vlo32[nbase + ((t0 + t) << 5) + vp];
                b = g_vlo32[nbase + ((t0 + t + 1) << 5) + vp];
                sVl[v * 68 + tp] = (a & 0xffffu) | (b << 16);
                sVl[(v + 1) * 68 + tp] = (a >> 16) | (b & 0xffff0000u);
            }
        }
        __syncthreads();

        float sacc[16][4];
#pragma unroll
        for (int j = 0; j < 16; j++)
#pragma unroll
            for (int e = 0; e < 4; e++) sacc[j][e] = 0.f;
#pragma unroll
        for (int j = 0; j < 16; j++) {
#pragma unroll
            for (int kc = 0; kc < 4; kc++) {
                const int bw = ((j << 3) + gid) * 36 + (kc << 3) + tig;
                uint32_t bh[2] = {sKh[bw], sKh[bw + 4]};
                uint32_t bl[2] = {sKl[bw], sKl[bw + 4]};
                mma16816(sacc[j], qhf[kc], bh);
                mma16816(sacc[j], qlf[kc], bh);
                mma16816(sacc[j], qhf[kc], bl);
            }
        }

        {
            float* h0p = heat + ((size_t)n << 20) + ((size_t)row0 << 10) + t0 + (tig << 1);
            float* h1p = heat + ((size_t)n << 20) + ((size_t)row1 << 10) + t0 + (tig << 1);
#pragma unroll
            for (int j = 0; j < 16; j++) {
                *(float2*)(h0p + (j << 3)) = make_float2(sacc[j][0], sacc[j][1]);
                *(float2*)(h1p + (j << 3)) = make_float2(sacc[j][2], sacc[j][3]);
            }
        }

        if (!causal) continue;

        if (tb == rb) {
#pragma unroll
            for (int j = 0; j < 16; j++) {
                const int c0 = t0 + (j << 3) + (tig << 1);
                if (c0 > row0) sacc[j][0] = -1e30f;
                if (c0 + 1 > row0) sacc[j][1] = -1e30f;
                if (c0 > row1) sacc[j][2] = -1e30f;
                if (c0 + 1 > row1) sacc[j][3] = -1e30f;
            }
        }

        float vm0 = -1e30f, vm1 = -1e30f;
#pragma unroll
        for (int j = 0; j < 16; j++) {
            vm0 = fmaxf(vm0, fmaxf(sacc[j][0], sacc[j][1]));
            vm1 = fmaxf(vm1, fmaxf(sacc[j][2], sacc[j][3]));
        }
        vm0 = fmaxf(vm0, __shfl_xor_sync(0xffffffffu, vm0, 1));
        vm0 = fmaxf(vm0, __shfl_xor_sync(0xffffffffu, vm0, 2));
        vm1 = fmaxf(vm1, __shfl_xor_sync(0xffffffffu, vm1, 1));
        vm1 = fmaxf(vm1, __shfl_xor_sync(0xffffffffu, vm1, 2));
        const float mn0 = fmaxf(m0, vm0), mn1 = fmaxf(m1, vm1);
        const float sc0 = __expf(m0 - mn0), sc1 = __expf(m1 - mn1);
        m0 = mn0; m1 = mn1;
        float rs0 = 0.f, rs1 = 0.f;
#pragma unroll
        for (int j = 0; j < 16; j++) {
            sacc[j][0] = __expf(sacc[j][0] - mn0);
            sacc[j][1] = __expf(sacc[j][1] - mn0);
            sacc[j][2] = __expf(sacc[j][2] - mn1);
            sacc[j][3] = __expf(sacc[j][3] - mn1);
            rs0 += sacc[j][0] + sacc[j][1];
            rs1 += sacc[j][2] + sacc[j][3];
        }
        rs0 += __shfl_xor_sync(0xffffffffu, rs0, 1);
        rs0 += __shfl_xor_sync(0xffffffffu, rs0, 2);
        rs1 += __shfl_xor_sync(0xffffffffu, rs1, 1);
        rs1 += __shfl_xor_sync(0xffffffffu, rs1, 2);
        l0 = l0 * sc0 + rs0;
        l1 = l1 * sc1 + rs1;
#pragma unroll
        for (int j = 0; j < 8; j++) {
            oacc[j][0] *= sc0; oacc[j][1] *= sc0;
            oacc[j][2] *= sc1; oacc[j][3] *= sc1;
        }

#pragma unroll
        for (int kt = 0; kt < 8; kt++) {
            uint32_t ph[4], pl[4];
            split2(sacc[2 * kt][0], sacc[2 * kt][1], ph[0], pl[0]);
            split2(sacc[2 * kt][2], sacc[2 * kt][3], ph[1], pl[1]);
            split2(sacc[2 * kt + 1][0], sacc[2 * kt + 1][1], ph[2], pl[2]);
            split2(sacc[2 * kt + 1][2], sacc[2 * kt + 1][3], ph[3], pl[3]);
#pragma unroll
            for (int j = 0; j < 8; j++) {
                const int bw = ((j << 3) + gid) * 68 + (kt << 3) + tig;
                uint32_t vh[2] = {sVh[bw], sVh[bw + 4]};
                uint32_t vl[2] = {sVl[bw], sVl[bw + 4]};
                mma16816(oacc[j], ph, vh);
                mma16816(oacc[j], pl, vh);
                mma16816(oacc[j], ph, vl);
            }
        }
    }

    const float i0 = 1.0f / l0, i1 = 1.0f / l1;
    const uint32_t wb0 = ((bb << 10) + row0) * 256 + (hh << 5) + tig;
    const uint32_t wb1 = ((bb << 10) + row1) * 256 + (hh << 5) + tig;
#pragma unroll
    for (int j = 0; j < 8; j++) {
        uint32_t hw, lw;
        split2(oacc[j][0] * i0, oacc[j][1] * i0, hw, lw);
        g_wvhi32[wb0 + (j << 2)] = hw;
        g_wvlo32[wb0 + (j << 2)] = lw;
        split2(oacc[j][2] * i1, oacc[j][3] * i1, hw, lw);
        g_wvhi32[wb1 + (j << 2)] = hw;
        g_wvlo32[wb1 + (j << 2)] = lw;
    }
}

// ---------------- launch ------------------------------------------------------
extern "C" void kernel_launch(void* const* d_in, const int* in_sizes, int n_in,
                              void* d_out, int out_size) {
    const float* x  = (const float*)d_in[0];
    const float* Wq = (const float*)d_in[1];
    const float* bq = (const float*)d_in[2];
    const float* Wk = (const float*)d_in[3];
    const float* bk = (const float*)d_in[4];
    const float* Wv = (const float*)d_in[5];
    const float* bv = (const float*)d_in[6];
    const float* Wo = (const float*)d_in[7];
    const float* bo = (const float*)d_in[8];

    float* out = (float*)d_out;
    float* heat = out + (size_t)8 * 1024 * 512;

    cudaFuncSetAttribute(attn_kernel, cudaFuncAttributeMaxDynamicSharedMemorySize,
                         AT_SMEM_BYTES);

    conv_x<<<4096, 256>>>(x);
    dim3 wtb(32, 32), wtg(16, 16);
    conv_wt<<<wtg, wtb>>>(Wq, 0);
    conv_wt<<<wtg, wtb>>>(Wk, 1);
    conv_wt<<<wtg, wtb>>>(Wv, 2);
    conv_wt<<<wtg, wtb>>>(Wo, 3);

    dim3 tg(4, 64);
    tgemm<<<tg, 256>>>(0, 0, bq, nullptr, 1);
    tgemm<<<tg, 256>>>(0, 1, bk, nullptr, 2);
    tgemm<<<tg, 256>>>(0, 2, bv, nullptr, 3);
    attn_kernel<<<dim3(8, 64), 256, AT_SMEM_BYTES>>>(heat);
    tgemm<<<tg, 256>>>(1, 3, bo, out, 0);
}

// round 6
// speedup vs baseline: 2.2400x; 1.0873x over previous
#include <cuda_runtime.h>
#include <cuda_bf16.h>
#include <cstdint>
#include <cstddef>

// B=8, S=1024, D=512, H=8, qdim=vdim=64, n=H*B=64
// d_out = out [8,1024,512] ++ heatmap [64,1024,1024]

// ---------------- scratch globals (bf16 pairs stored as u32 words) ------------
__device__ uint32_t g_qhi32[64ull * 1024 * 32], g_qlo32[64ull * 1024 * 32];
__device__ uint32_t g_khi32[64ull * 1024 * 32], g_klo32[64ull * 1024 * 32];
__device__ uint32_t g_vhi32[64ull * 1024 * 32], g_vlo32[64ull * 1024 * 32];
__device__ uint32_t g_wvhi32[8192ull * 256], g_wvlo32[8192ull * 256];
__device__ __nv_bfloat16 g_xhi[8192ull * 512], g_xlo[8192ull * 512];
__device__ __nv_bfloat16 g_wth[4][512 * 512], g_wtl[4][512 * 512];

// ---------------- helpers ------------------------------------------------------
__device__ __forceinline__ void mma16816(float* c, const uint32_t* a, const uint32_t* b) {
    asm volatile(
        "mma.sync.aligned.m16n8k16.row.col.f32.bf16.bf16.f32 "
        "{%0,%1,%2,%3}, {%4,%5,%6,%7}, {%8,%9}, {%0,%1,%2,%3};"
        : "+f"(c[0]), "+f"(c[1]), "+f"(c[2]), "+f"(c[3])
        : "r"(a[0]), "r"(a[1]), "r"(a[2]), "r"(a[3]), "r"(b[0]), "r"(b[1]));
}
__device__ __forceinline__ uint32_t packbf(float lo, float hi) {
    uint32_t r;
    asm("cvt.rn.bf16x2.f32 %0, %1, %2;" : "=r"(r) : "f"(hi), "f"(lo));
    return r;
}
__device__ __forceinline__ void split2(float a, float b, uint32_t& hw, uint32_t& lw) {
    uint32_t h = packbf(a, b);
    __nv_bfloat162 h2 = *reinterpret_cast<__nv_bfloat162*>(&h);
    float ra = a - __low2float(h2);
    float rb = b - __high2float(h2);
    hw = h;
    lw = packbf(ra, rb);
}
__device__ __forceinline__ uint32_t smem_u32(const void* p) {
    uint32_t a;
    asm("{ .reg .u64 t; cvta.to.shared.u64 t, %1; cvt.u32.u64 %0, t; }" : "=r"(a) : "l"(p));
    return a;
}
__device__ __forceinline__ void cpasync16(uint32_t saddr, const void* gptr) {
    asm volatile("cp.async.ca.shared.global [%0], [%1], 16;" :: "r"(saddr), "l"(gptr));
}
#define CP_COMMIT() asm volatile("cp.async.commit_group;" ::: "memory")
#define CP_WAIT(n) asm volatile("cp.async.wait_group %0;" :: "n"(n) : "memory")

// ---------------- conversion kernels ------------------------------------------
__global__ __launch_bounds__(256) void conv_x(const float* __restrict__ X) {
    size_t i = ((size_t)blockIdx.x * 256 + threadIdx.x) * 4;
    float4 v = *(const float4*)(X + i);
    uint32_t h0, l0, h1, l1;
    split2(v.x, v.y, h0, l0);
    split2(v.z, v.w, h1, l1);
    *(uint32_t*)(g_xhi + i) = h0;
    *(uint32_t*)(g_xhi + i + 2) = h1;
    *(uint32_t*)(g_xlo + i) = l0;
    *(uint32_t*)(g_xlo + i + 2) = l1;
}

// all 4 weights in one launch: grid (16,16,4)
__global__ void conv_wt(const float* __restrict__ W0, const float* __restrict__ W1,
                        const float* __restrict__ W2, const float* __restrict__ W3) {
    __shared__ float t[32][33];
    const int widx = blockIdx.z;
    const float* W = (widx == 0) ? W0 : (widx == 1) ? W1 : (widx == 2) ? W2 : W3;
    int k = blockIdx.y * 32 + threadIdx.y;
    int n = blockIdx.x * 32 + threadIdx.x;
    t[threadIdx.y][threadIdx.x] = W[(size_t)k * 512 + n];
    __syncthreads();
    int n2 = blockIdx.x * 32 + threadIdx.y;
    int k2 = blockIdx.y * 32 + threadIdx.x;
    float v = t[threadIdx.x][threadIdx.y];
    __nv_bfloat16 h = __float2bfloat16_rn(v);
    g_wth[widx][(size_t)n2 * 512 + k2] = h;
    g_wtl[widx][(size_t)n2 * 512 + k2] = __float2bfloat16_rn(v - __bfloat162float(h));
}

// ---------------- HMMA split-bf16 GEMM (cp.async double-buffered) -------------
// grid (4, 64, Z). z selects weight widx0+z / bias / dest mode.
// mode0=1: qkv (modes 1,2,3). mode0=0: out proj (Z=1).
#define TPAD 40
#define TG_ARR (128 * TPAD)            // bf16 per array per stage
#define TG_STAGE (4 * TG_ARR)          // bf16 per stage
#define TG_SMEM_BYTES (2 * TG_STAGE * 2)

__device__ __forceinline__ void tg_issue(uint32_t sb, int stage,
                                         const __nv_bfloat16* __restrict__ Ah,
                                         const __nv_bfloat16* __restrict__ Al,
                                         const __nv_bfloat16* __restrict__ Bh,
                                         const __nv_bfloat16* __restrict__ Bl,
                                         int m0, int n0, int k0, int tid) {
    const int row = tid >> 1, half = tid & 1;
    const uint32_t base = sb + stage * (TG_STAGE * 2);
    const uint32_t doff = (uint32_t)(row * TPAD + half * 16) * 2;
    const __nv_bfloat16* srcs[4] = {
        Ah + (size_t)(m0 + row) * 512 + k0 + half * 16,
        Al + (size_t)(m0 + row) * 512 + k0 + half * 16,
        Bh + (size_t)(n0 + row) * 512 + k0 + half * 16,
        Bl + (size_t)(n0 + row) * 512 + k0 + half * 16};
#pragma unroll
    for (int a = 0; a < 4; a++) {
        uint32_t d = base + a * (TG_ARR * 2) + doff;
        cpasync16(d, srcs[a]);
        cpasync16(d + 16, (const char*)srcs[a] + 16);
    }
}

__global__ __launch_bounds__(256) void tgemm(int asel, int widx0,
                                             const float* __restrict__ bz0,
                                             const float* __restrict__ bz1,
                                             const float* __restrict__ bz2,
                                             float* __restrict__ outp, int mode0) {
    extern __shared__ __nv_bfloat16 smem[];
    const uint32_t sb = smem_u32(smem);

    const int z = blockIdx.z;
    const int widx = widx0 + z;
    const int mode = mode0 ? mode0 + z : 0;
    const float* bias = (z == 0) ? bz0 : (z == 1) ? bz1 : bz2;

    const int tid = threadIdx.x;
    const int wid = tid >> 5, lane = tid & 31;
    const int gid = lane >> 2, tig = lane & 3;
    const int wm0 = (wid >> 2) << 6;
    const int wn0 = (wid & 3) << 5;
    const int n0 = blockIdx.x << 7, m0 = blockIdx.y << 7;

    const __nv_bfloat16* Ah = asel ? (const __nv_bfloat16*)g_wvhi32 : g_xhi;
    const __nv_bfloat16* Al = asel ? (const __nv_bfloat16*)g_wvlo32 : g_xlo;
    const __nv_bfloat16* Bh = g_wth[widx];
    const __nv_bfloat16* Bl = g_wtl[widx];

    float acc[4][4][4];
#pragma unroll
    for (int i = 0; i < 4; i++)
#pragma unroll
        for (int j = 0; j < 4; j++)
#pragma unroll
            for (int e = 0; e < 4; e++) acc[i][j][e] = 0.f;

    tg_issue(sb, 0, Ah, Al, Bh, Bl, m0, n0, 0, tid);
    CP_COMMIT();

    for (int c = 0; c < 16; c++) {
        __syncthreads();  // prior compute done; safe to overwrite buffer (c+1)&1
        if (c + 1 < 16) {
            tg_issue(sb, (c + 1) & 1, Ah, Al, Bh, Bl, m0, n0, (c + 1) << 5, tid);
            CP_COMMIT();
            CP_WAIT(1);
        } else {
            CP_WAIT(0);
        }
        __syncthreads();

        const __nv_bfloat16* st = smem + (c & 1) * TG_STAGE;
        const __nv_bfloat16* sAh = st;
        const __nv_bfloat16* sAl = st + TG_ARR;
        const __nv_bfloat16* sBh = st + 2 * TG_ARR;
        const __nv_bfloat16* sBl = st + 3 * TG_ARR;

#pragma unroll
        for (int ks = 0; ks < 32; ks += 16) {
            uint32_t ah[4][4], al[4][4], bh[4][2], bl[4][2];
            const int cb = ks + (tig << 1);
#pragma unroll
            for (int i = 0; i < 4; i++) {
                const int r = wm0 + (i << 4) + gid;
                ah[i][0] = *(const uint32_t*)&sAh[r * TPAD + cb];
                ah[i][1] = *(const uint32_t*)&sAh[(r + 8) * TPAD + cb];
                ah[i][2] = *(const uint32_t*)&sAh[r * TPAD + cb + 8];
                ah[i][3] = *(const uint32_t*)&sAh[(r + 8) * TPAD + cb + 8];
                al[i][0] = *(const uint32_t*)&sAl[r * TPAD + cb];
                al[i][1] = *(const uint32_t*)&sAl[(r + 8) * TPAD + cb];
                al[i][2] = *(const uint32_t*)&sAl[r * TPAD + cb + 8];
                al[i][3] = *(const uint32_t*)&sAl[(r + 8) * TPAD + cb + 8];
            }
#pragma unroll
            for (int j = 0; j < 4; j++) {
                const int n = wn0 + (j << 3) + gid;
                bh[j][0] = *(const uint32_t*)&sBh[n * TPAD + cb];
                bh[j][1] = *(const uint32_t*)&sBh[n * TPAD + cb + 8];
                bl[j][0] = *(const uint32_t*)&sBl[n * TPAD + cb];
                bl[j][1] = *(const uint32_t*)&sBl[n * TPAD + cb + 8];
            }
#pragma unroll
            for (int i = 0; i < 4; i++)
#pragma unroll
                for (int j = 0; j < 4; j++) {
                    mma16816(acc[i][j], ah[i], bh[j]);
                    mma16816(acc[i][j], ah[i], bl[j]);
                    mma16816(acc[i][j], al[i], bh[j]);
                }
        }
    }

    uint32_t* qh = (mode == 1) ? g_qhi32 : (mode == 2) ? g_khi32 : g_vhi32;
    uint32_t* ql = (mode == 1) ? g_qlo32 : (mode == 2) ? g_klo32 : g_vlo32;
#pragma unroll
    for (int i = 0; i < 4; i++) {
        const int r = m0 + wm0 + (i << 4) + gid;
#pragma unroll
        for (int j = 0; j < 4; j++) {
            const int col = n0 + wn0 + (j << 3) + (tig << 1);
            const float b0 = bias[col], b1 = bias[col + 1];
            float w00 = acc[i][j][0] + b0, w01 = acc[i][j][1] + b1;
            float w10 = acc[i][j][2] + b0, w11 = acc[i][j][3] + b1;
            if (mode == 0) {
                *(float2*)(outp + (size_t)r * 512 + col) = make_float2(w00, w01);
                *(float2*)(outp + (size_t)(r + 8) * 512 + col) = make_float2(w10, w11);
            } else {
                const int h = col >> 6, d = col & 63;
                const int bb = r >> 10, s = r & 1023;
                size_t w = (((size_t)(h * 8 + bb)) << 15) + ((size_t)s << 5) + (d >> 1);
                uint32_t hw, lw;
                split2(w00, w01, hw, lw);
                qh[w] = hw; ql[w] = lw;
                split2(w10, w11, hw, lw);
                qh[w + 256] = hw; ql[w + 256] = lw;  // row s+8
            }
        }
    }
}

// ---------------- tensorized fused attention + heatmap ------------------------
#define AT_SMEM_BYTES ((4608 * 2 + 4352 * 2) * 4)

__global__ __launch_bounds__(256) void attn_kernel(float* __restrict__ heat) {
    extern __shared__ uint32_t sm[];
    uint32_t* sKh = sm;
    uint32_t* sKl = sm + 4608;
    uint32_t* sVh = sm + 9216;
    uint32_t* sVl = sm + 13568;

    const int tid = threadIdx.x;
    const int wid = tid >> 5, lane = tid & 31;
    const int gid = lane >> 2, tig = lane & 3;
    const int rb = blockIdx.x, n = blockIdx.y;
    const int r0 = rb << 7, wr = wid << 4;
    const int hh = n >> 3, bb = n & 7;
    const uint32_t nbase = n << 15;

#pragma unroll
    for (int i = 0; i < 16; i++) {
        int idx = tid + (i << 8);
        int r = idx >> 5, c = idx & 31;
        sKh[r * 36 + c] = g_qhi32[nbase + ((r0 + r) << 5) + c];
        sKl[r * 36 + c] = g_qlo32[nbase + ((r0 + r) << 5) + c];
    }
    __syncthreads();
    uint32_t qhf[4][4], qlf[4][4];
#pragma unroll
    for (int kc = 0; kc < 4; kc++) {
        int b0 = (wr + gid) * 36 + (kc << 3) + tig;
        int b1 = (wr + gid + 8) * 36 + (kc << 3) + tig;
        qhf[kc][0] = sKh[b0]; qhf[kc][1] = sKh[b1];
        qhf[kc][2] = sKh[b0 + 4]; qhf[kc][3] = sKh[b1 + 4];
        qlf[kc][0] = sKl[b0]; qlf[kc][1] = sKl[b1];
        qlf[kc][2] = sKl[b0 + 4]; qlf[kc][3] = sKl[b1 + 4];
    }

    float m0 = -1e30f, m1 = -1e30f, l0 = 0.f, l1 = 0.f;
    float oacc[8][4];
#pragma unroll
    for (int j = 0; j < 8; j++)
#pragma unroll
        for (int e = 0; e < 4; e++) oacc[j][e] = 0.f;

    const int row0 = r0 + wr + gid, row1 = row0 + 8;

    for (int tb = 0; tb < 8; tb++) {
        const int t0 = tb << 7;
        const bool causal = (tb <= rb);
        __syncthreads();
#pragma unroll
        for (int i = 0; i < 16; i++) {
            int idx = tid + (i << 8);
            int r = idx >> 5, c = idx & 31;
            sKh[r * 36 + c] = g_khi32[nbase + ((t0 + r) << 5) + c];
            sKl[r * 36 + c] = g_klo32[nbase + ((t0 + r) << 5) + c];
        }
        if (causal) {
            const int tp = tid >> 2;
            const int t = tp << 1;
#pragma unroll
            for (int i = 0; i < 8; i++) {
                const int vp = (tid & 3) + (i << 2);
                const int v = vp << 1;
                uint32_t a = g_vhi32[nbase + ((t0 + t) << 5) + vp];
                uint32_t b = g_vhi32[nbase + ((t0 + t + 1) << 5) + vp];
                sVh[v * 68 + tp] = (a & 0xffffu) | (b << 16);
                sVh[(v + 1) * 68 + tp] = (a >> 16) | (b & 0xffff0000u);
                a = g_vlo32[nbase + ((t0 + t) << 5) + vp];
                b = g_vlo32[nbase + ((t0 + t + 1) << 5) + vp];
                sVl[v * 68 + tp] = (a & 0xffffu) | (b << 16);
                sVl[(v + 1) * 68 + tp] = (a >> 16) | (b & 0xffff0000u);
            }
        }
        __syncthreads();

        float sacc[16][4];
#pragma unroll
        for (int j = 0; j < 16; j++)
#pragma unroll
            for (int e = 0; e < 4; e++) sacc[j][e] = 0.f;
#pragma unroll
        for (int j = 0; j < 16; j++) {
#pragma unroll
            for (int kc = 0; kc < 4; kc++) {
                const int bw = ((j << 3) + gid) * 36 + (kc << 3) + tig;
                uint32_t bh[2] = {sKh[bw], sKh[bw + 4]};
                uint32_t bl[2] = {sKl[bw], sKl[bw + 4]};
                mma16816(sacc[j], qhf[kc], bh);
                mma16816(sacc[j], qlf[kc], bh);
                mma16816(sacc[j], qhf[kc], bl);
            }
        }

        {
            float* h0p = heat + ((size_t)n << 20) + ((size_t)row0 << 10) + t0 + (tig << 1);
            float* h1p = heat + ((size_t)n << 20) + ((size_t)row1 << 10) + t0 + (tig << 1);
#pragma unroll
            for (int j = 0; j < 16; j++) {
                *(float2*)(h0p + (j << 3)) = make_float2(sacc[j][0], sacc[j][1]);
                *(float2*)(h1p + (j << 3)) = make_float2(sacc[j][2], sacc[j][3]);
            }
        }

        if (!causal) continue;

        if (tb == rb) {
#pragma unroll
            for (int j = 0; j < 16; j++) {
                const int c0 = t0 + (j << 3) + (tig << 1);
                if (c0 > row0) sacc[j][0] = -1e30f;
                if (c0 + 1 > row0) sacc[j][1] = -1e30f;
                if (c0 > row1) sacc[j][2] = -1e30f;
                if (c0 + 1 > row1) sacc[j][3] = -1e30f;
            }
        }

        float vm0 = -1e30f, vm1 = -1e30f;
#pragma unroll
        for (int j = 0; j < 16; j++) {
            vm0 = fmaxf(vm0, fmaxf(sacc[j][0], sacc[j][1]));
            vm1 = fmaxf(vm1, fmaxf(sacc[j][2], sacc[j][3]));
        }
        vm0 = fmaxf(vm0, __shfl_xor_sync(0xffffffffu, vm0, 1));
        vm0 = fmaxf(vm0, __shfl_xor_sync(0xffffffffu, vm0, 2));
        vm1 = fmaxf(vm1, __shfl_xor_sync(0xffffffffu, vm1, 1));
        vm1 = fmaxf(vm1, __shfl_xor_sync(0xffffffffu, vm1, 2));
        const float mn0 = fmaxf(m0, vm0), mn1 = fmaxf(m1, vm1);
        const float sc0 = __expf(m0 - mn0), sc1 = __expf(m1 - mn1);
        m0 = mn0; m1 = mn1;
        float rs0 = 0.f, rs1 = 0.f;
#pragma unroll
        for (int j = 0; j < 16; j++) {
            sacc[j][0] = __expf(sacc[j][0] - mn0);
            sacc[j][1] = __expf(sacc[j][1] - mn0);
            sacc[j][2] = __expf(sacc[j][2] - mn1);
            sacc[j][3] = __expf(sacc[j][3] - mn1);
            rs0 += sacc[j][0] + sacc[j][1];
            rs1 += sacc[j][2] + sacc[j][3];
        }
        rs0 += __shfl_xor_sync(0xffffffffu, rs0, 1);
        rs0 += __shfl_xor_sync(0xffffffffu, rs0, 2);
        rs1 += __shfl_xor_sync(0xffffffffu, rs1, 1);
        rs1 += __shfl_xor_sync(0xffffffffu, rs1, 2);
        l0 = l0 * sc0 + rs0;
        l1 = l1 * sc1 + rs1;
#pragma unroll
        for (int j = 0; j < 8; j++) {
            oacc[j][0] *= sc0; oacc[j][1] *= sc0;
            oacc[j][2] *= sc1; oacc[j][3] *= sc1;
        }

#pragma unroll
        for (int kt = 0; kt < 8; kt++) {
            uint32_t ph[4], pl[4];
            split2(sacc[2 * kt][0], sacc[2 * kt][1], ph[0], pl[0]);
            split2(sacc[2 * kt][2], sacc[2 * kt][3], ph[1], pl[1]);
            split2(sacc[2 * kt + 1][0], sacc[2 * kt + 1][1], ph[2], pl[2]);
            split2(sacc[2 * kt + 1][2], sacc[2 * kt + 1][3], ph[3], pl[3]);
#pragma unroll
            for (int j = 0; j < 8; j++) {
                const int bw = ((j << 3) + gid) * 68 + (kt << 3) + tig;
                uint32_t vh[2] = {sVh[bw], sVh[bw + 4]};
                uint32_t vl[2] = {sVl[bw], sVl[bw + 4]};
                mma16816(oacc[j], ph, vh);
                mma16816(oacc[j], pl, vh);
                mma16816(oacc[j], ph, vl);
            }
        }
    }

    const float i0 = 1.0f / l0, i1 = 1.0f / l1;
    const uint32_t wb0 = ((bb << 10) + row0) * 256 + (hh << 5) + tig;
    const uint32_t wb1 = ((bb << 10) + row1) * 256 + (hh << 5) + tig;
#pragma unroll
    for (int j = 0; j < 8; j++) {
        uint32_t hw, lw;
        split2(oacc[j][0] * i0, oacc[j][1] * i0, hw, lw);
        g_wvhi32[wb0 + (j << 2)] = hw;
        g_wvlo32[wb0 + (j << 2)] = lw;
        split2(oacc[j][2] * i1, oacc[j][3] * i1, hw, lw);
        g_wvhi32[wb1 + (j << 2)] = hw;
        g_wvlo32[wb1 + (j << 2)] = lw;
    }
}

// ---------------- launch ------------------------------------------------------
extern "C" void kernel_launch(void* const* d_in, const int* in_sizes, int n_in,
                              void* d_out, int out_size) {
    const float* x  = (const float*)d_in[0];
    const float* Wq = (const float*)d_in[1];
    const float* bq = (const float*)d_in[2];
    const float* Wk = (const float*)d_in[3];
    const float* bk = (const float*)d_in[4];
    const float* Wv = (const float*)d_in[5];
    const float* bv = (const float*)d_in[6];
    const float* Wo = (const float*)d_in[7];
    const float* bo = (const float*)d_in[8];

    float* out = (float*)d_out;
    float* heat = out + (size_t)8 * 1024 * 512;

    cudaFuncSetAttribute(attn_kernel, cudaFuncAttributeMaxDynamicSharedMemorySize,
                         AT_SMEM_BYTES);
    cudaFuncSetAttribute(tgemm, cudaFuncAttributeMaxDynamicSharedMemorySize,
                         TG_SMEM_BYTES);

    conv_x<<<4096, 256>>>(x);
    conv_wt<<<dim3(16, 16, 4), dim3(32, 32)>>>(Wq, Wk, Wv, Wo);

    tgemm<<<dim3(4, 64, 3), 256, TG_SMEM_BYTES>>>(0, 0, bq, bk, bv, nullptr, 1);
    attn_kernel<<<dim3(8, 64), 256, AT_SMEM_BYTES>>>(heat);
    tgemm<<<dim3(4, 64, 1), 256, TG_SMEM_BYTES>>>(1, 3, bo, nullptr, nullptr, out, 0);
}

// round 7
// speedup vs baseline: 2.4621x; 1.0991x over previous
#include <cuda_runtime.h>
#include <cuda_bf16.h>
#include <cstdint>
#include <cstddef>

// B=8, S=1024, D=512, H=8, qdim=vdim=64, n=H*B=64
// d_out = out [8,1024,512] ++ heatmap [64,1024,1024]

// ---------------- scratch globals (bf16 pairs stored as u32 words) ------------
__device__ uint32_t g_qhi32[64ull * 1024 * 32], g_qlo32[64ull * 1024 * 32];
__device__ uint32_t g_khi32[64ull * 1024 * 32], g_klo32[64ull * 1024 * 32];
__device__ uint32_t g_vhi32[64ull * 1024 * 32], g_vlo32[64ull * 1024 * 32];
__device__ uint32_t g_wvhi32[8192ull * 256], g_wvlo32[8192ull * 256];
__device__ __nv_bfloat16 g_xhi[8192ull * 512], g_xlo[8192ull * 512];
__device__ __nv_bfloat16 g_wth[4][512 * 512], g_wtl[4][512 * 512];

// ---------------- helpers ------------------------------------------------------
__device__ __forceinline__ void mma16816(float* c, const uint32_t* a, const uint32_t* b) {
    asm volatile(
        "mma.sync.aligned.m16n8k16.row.col.f32.bf16.bf16.f32 "
        "{%0,%1,%2,%3}, {%4,%5,%6,%7}, {%8,%9}, {%0,%1,%2,%3};"
        : "+f"(c[0]), "+f"(c[1]), "+f"(c[2]), "+f"(c[3])
        : "r"(a[0]), "r"(a[1]), "r"(a[2]), "r"(a[3]), "r"(b[0]), "r"(b[1]));
}
__device__ __forceinline__ uint32_t packbf(float lo, float hi) {
    uint32_t r;
    asm("cvt.rn.bf16x2.f32 %0, %1, %2;" : "=r"(r) : "f"(hi), "f"(lo));
    return r;
}
__device__ __forceinline__ void split2(float a, float b, uint32_t& hw, uint32_t& lw) {
    uint32_t h = packbf(a, b);
    __nv_bfloat162 h2 = *reinterpret_cast<__nv_bfloat162*>(&h);
    float ra = a - __low2float(h2);
    float rb = b - __high2float(h2);
    hw = h;
    lw = packbf(ra, rb);
}
__device__ __forceinline__ uint32_t smem_u32(const void* p) {
    uint32_t a;
    asm("{ .reg .u64 t; cvta.to.shared.u64 t, %1; cvt.u32.u64 %0, t; }" : "=r"(a) : "l"(p));
    return a;
}
__device__ __forceinline__ void cpasync16(uint32_t saddr, const void* gptr) {
    asm volatile("cp.async.ca.shared.global [%0], [%1], 16;" :: "r"(saddr), "l"(gptr));
}
#define CP_COMMIT() asm volatile("cp.async.commit_group;" ::: "memory")
#define CP_WAIT(n) asm volatile("cp.async.wait_group %0;" :: "n"(n) : "memory")
__device__ __forceinline__ void ldm_x4(uint32_t* r, uint32_t addr) {
    asm volatile("ldmatrix.sync.aligned.m8n8.x4.shared.b16 {%0,%1,%2,%3}, [%4];"
                 : "=r"(r[0]), "=r"(r[1]), "=r"(r[2]), "=r"(r[3]) : "r"(addr));
}
__device__ __forceinline__ void ldm_x4_t(uint32_t* r, uint32_t addr) {
    asm volatile("ldmatrix.sync.aligned.m8n8.x4.trans.shared.b16 {%0,%1,%2,%3}, [%4];"
                 : "=r"(r[0]), "=r"(r[1]), "=r"(r[2]), "=r"(r[3]) : "r"(addr));
}

// ---------------- conversion kernels ------------------------------------------
__global__ __launch_bounds__(256) void conv_x(const float* __restrict__ X) {
    size_t i = ((size_t)blockIdx.x * 256 + threadIdx.x) * 4;
    float4 v = *(const float4*)(X + i);
    uint32_t h0, l0, h1, l1;
    split2(v.x, v.y, h0, l0);
    split2(v.z, v.w, h1, l1);
    *(uint32_t*)(g_xhi + i) = h0;
    *(uint32_t*)(g_xhi + i + 2) = h1;
    *(uint32_t*)(g_xlo + i) = l0;
    *(uint32_t*)(g_xlo + i + 2) = l1;
}

__global__ void conv_wt(const float* __restrict__ W0, const float* __restrict__ W1,
                        const float* __restrict__ W2, const float* __restrict__ W3) {
    __shared__ float t[32][33];
    const int widx = blockIdx.z;
    const float* W = (widx == 0) ? W0 : (widx == 1) ? W1 : (widx == 2) ? W2 : W3;
    int k = blockIdx.y * 32 + threadIdx.y;
    int n = blockIdx.x * 32 + threadIdx.x;
    t[threadIdx.y][threadIdx.x] = W[(size_t)k * 512 + n];
    __syncthreads();
    int n2 = blockIdx.x * 32 + threadIdx.y;
    int k2 = blockIdx.y * 32 + threadIdx.x;
    float v = t[threadIdx.x][threadIdx.y];
    __nv_bfloat16 h = __float2bfloat16_rn(v);
    g_wth[widx][(size_t)n2 * 512 + k2] = h;
    g_wtl[widx][(size_t)n2 * 512 + k2] = __float2bfloat16_rn(v - __bfloat162float(h));
}

// ---------------- HMMA split-bf16 GEMM (cp.async double-buffered) -------------
#define TPAD 40
#define TG_ARR (128 * TPAD)
#define TG_STAGE (4 * TG_ARR)
#define TG_SMEM_BYTES (2 * TG_STAGE * 2)

__device__ __forceinline__ void tg_issue(uint32_t sb, int stage,
                                         const __nv_bfloat16* __restrict__ Ah,
                                         const __nv_bfloat16* __restrict__ Al,
                                         const __nv_bfloat16* __restrict__ Bh,
                                         const __nv_bfloat16* __restrict__ Bl,
                                         int m0, int n0, int k0, int tid) {
    const int row = tid >> 1, half = tid & 1;
    const uint32_t base = sb + stage * (TG_STAGE * 2);
    const uint32_t doff = (uint32_t)(row * TPAD + half * 16) * 2;
    const __nv_bfloat16* srcs[4] = {
        Ah + (size_t)(m0 + row) * 512 + k0 + half * 16,
        Al + (size_t)(m0 + row) * 512 + k0 + half * 16,
        Bh + (size_t)(n0 + row) * 512 + k0 + half * 16,
        Bl + (size_t)(n0 + row) * 512 + k0 + half * 16};
#pragma unroll
    for (int a = 0; a < 4; a++) {
        uint32_t d = base + a * (TG_ARR * 2) + doff;
        cpasync16(d, srcs[a]);
        cpasync16(d + 16, (const char*)srcs[a] + 16);
    }
}

__global__ __launch_bounds__(256) void tgemm(int asel, int widx0,
                                             const float* __restrict__ bz0,
                                             const float* __restrict__ bz1,
                                             const float* __restrict__ bz2,
                                             float* __restrict__ outp, int mode0) {
    extern __shared__ __nv_bfloat16 smem[];
    const uint32_t sb = smem_u32(smem);

    const int z = blockIdx.z;
    const int widx = widx0 + z;
    const int mode = mode0 ? mode0 + z : 0;
    const float* bias = (z == 0) ? bz0 : (z == 1) ? bz1 : bz2;

    const int tid = threadIdx.x;
    const int wid = tid >> 5, lane = tid & 31;
    const int gid = lane >> 2, tig = lane & 3;
    const int wm0 = (wid >> 2) << 6;
    const int wn0 = (wid & 3) << 5;
    const int n0 = blockIdx.x << 7, m0 = blockIdx.y << 7;

    const __nv_bfloat16* Ah = asel ? (const __nv_bfloat16*)g_wvhi32 : g_xhi;
    const __nv_bfloat16* Al = asel ? (const __nv_bfloat16*)g_wvlo32 : g_xlo;
    const __nv_bfloat16* Bh = g_wth[widx];
    const __nv_bfloat16* Bl = g_wtl[widx];

    float acc[4][4][4];
#pragma unroll
    for (int i = 0; i < 4; i++)
#pragma unroll
        for (int j = 0; j < 4; j++)
#pragma unroll
            for (int e = 0; e < 4; e++) acc[i][j][e] = 0.f;

    tg_issue(sb, 0, Ah, Al, Bh, Bl, m0, n0, 0, tid);
    CP_COMMIT();

    for (int c = 0; c < 16; c++) {
        __syncthreads();
        if (c + 1 < 16) {
            tg_issue(sb, (c + 1) & 1, Ah, Al, Bh, Bl, m0, n0, (c + 1) << 5, tid);
            CP_COMMIT();
            CP_WAIT(1);
        } else {
            CP_WAIT(0);
        }
        __syncthreads();

        const __nv_bfloat16* st = smem + (c & 1) * TG_STAGE;
        const __nv_bfloat16* sAh = st;
        const __nv_bfloat16* sAl = st + TG_ARR;
        const __nv_bfloat16* sBh = st + 2 * TG_ARR;
        const __nv_bfloat16* sBl = st + 3 * TG_ARR;

#pragma unroll
        for (int ks = 0; ks < 32; ks += 16) {
            uint32_t ah[4][4], al[4][4], bh[4][2], bl[4][2];
            const int cb = ks + (tig << 1);
#pragma unroll
            for (int i = 0; i < 4; i++) {
                const int r = wm0 + (i << 4) + gid;
                ah[i][0] = *(const uint32_t*)&sAh[r * TPAD + cb];
                ah[i][1] = *(const uint32_t*)&sAh[(r + 8) * TPAD + cb];
                ah[i][2] = *(const uint32_t*)&sAh[r * TPAD + cb + 8];
                ah[i][3] = *(const uint32_t*)&sAh[(r + 8) * TPAD + cb + 8];
                al[i][0] = *(const uint32_t*)&sAl[r * TPAD + cb];
                al[i][1] = *(const uint32_t*)&sAl[(r + 8) * TPAD + cb];
                al[i][2] = *(const uint32_t*)&sAl[r * TPAD + cb + 8];
                al[i][3] = *(const uint32_t*)&sAl[(r + 8) * TPAD + cb + 8];
            }
#pragma unroll
            for (int j = 0; j < 4; j++) {
                const int n = wn0 + (j << 3) + gid;
                bh[j][0] = *(const uint32_t*)&sBh[n * TPAD + cb];
                bh[j][1] = *(const uint32_t*)&sBh[n * TPAD + cb + 8];
                bl[j][0] = *(const uint32_t*)&sBl[n * TPAD + cb];
                bl[j][1] = *(const uint32_t*)&sBl[n * TPAD + cb + 8];
            }
#pragma unroll
            for (int i = 0; i < 4; i++)
#pragma unroll
                for (int j = 0; j < 4; j++) {
                    mma16816(acc[i][j], ah[i], bh[j]);
                    mma16816(acc[i][j], ah[i], bl[j]);
                    mma16816(acc[i][j], al[i], bh[j]);
                }
        }
    }

    uint32_t* qh = (mode == 1) ? g_qhi32 : (mode == 2) ? g_khi32 : g_vhi32;
    uint32_t* ql = (mode == 1) ? g_qlo32 : (mode == 2) ? g_klo32 : g_vlo32;
#pragma unroll
    for (int i = 0; i < 4; i++) {
        const int r = m0 + wm0 + (i << 4) + gid;
#pragma unroll
        for (int j = 0; j < 4; j++) {
            const int col = n0 + wn0 + (j << 3) + (tig << 1);
            const float b0 = bias[col], b1 = bias[col + 1];
            float w00 = acc[i][j][0] + b0, w01 = acc[i][j][1] + b1;
            float w10 = acc[i][j][2] + b0, w11 = acc[i][j][3] + b1;
            if (mode == 0) {
                *(float2*)(outp + (size_t)r * 512 + col) = make_float2(w00, w01);
                *(float2*)(outp + (size_t)(r + 8) * 512 + col) = make_float2(w10, w11);
            } else {
                const int h = col >> 6, d = col & 63;
                const int bb = r >> 10, s = r & 1023;
                size_t w = (((size_t)(h * 8 + bb)) << 15) + ((size_t)s << 5) + (d >> 1);
                uint32_t hw, lw;
                split2(w00, w01, hw, lw);
                qh[w] = hw; ql[w] = lw;
                split2(w10, w11, hw, lw);
                qh[w + 256] = hw; ql[w + 256] = lw;
            }
        }
    }
}

// ---------------- tensorized fused attention + heatmap ------------------------
// Double-buffered cp.async K/V tiles + ldmatrix fragments.
// Per stage (words): sKh[0,4608) sKl[4608,9216) sVh[9216,13824) sVl[13824,18432)
// pitch 36 words/row (144B, 16B-aligned, conflict-free for ldmatrix).
#define AT_P 36
#define AT_SKL 4608
#define AT_SVH 9216
#define AT_SVL 13824
#define AT_STW 18432
#define AT_SMEM_BYTES (2 * AT_STW * 4)

__device__ __forceinline__ void at_issue(uint32_t sb, int stage, uint32_t nbase,
                                         int t0, bool withV, int tid) {
    const uint32_t stb = sb + stage * (AT_STW * 4);
#pragma unroll
    for (int i = 0; i < 4; i++) {
        const int c = tid + (i << 8);
        const int row = c >> 3, seg = c & 7;
        const uint32_t w4 = (uint32_t)(row * AT_P + seg * 4) * 4;
        const uint32_t goff = nbase + ((t0 + row) << 5) + (seg << 2);
        cpasync16(stb + w4, g_khi32 + goff);
        cpasync16(stb + AT_SKL * 4 + w4, g_klo32 + goff);
        if (withV) {
            cpasync16(stb + AT_SVH * 4 + w4, g_vhi32 + goff);
            cpasync16(stb + AT_SVL * 4 + w4, g_vlo32 + goff);
        }
    }
}

__global__ __launch_bounds__(256) void attn_kernel(float* __restrict__ heat) {
    extern __shared__ uint32_t sm[];
    const uint32_t sb = smem_u32(sm);

    const int tid = threadIdx.x;
    const int wid = tid >> 5, lane = tid & 31;
    const int gid = lane >> 2, tig = lane & 3;
    const int rb = blockIdx.x, n = blockIdx.y;
    const int r0 = rb << 7, wr = wid << 4;
    const int hh = n >> 3, bb = n & 7;
    const uint32_t nbase = n << 15;

    // per-lane ldmatrix base offsets (words)
    const int sel = lane >> 3, lrow = lane & 7;
    const uint32_t kfl = ((sel & 2) ? AT_SKL : 0) + lrow * AT_P + ((sel & 1) << 2);
    const uint32_t vfl = ((sel & 2) ? AT_SVL : AT_SVH) + (((sel & 1) << 3) + lrow) * AT_P;

    // ---- stage Q into stage-1 K region via cp.async ----
    {
        const uint32_t qstb = sb + AT_STW * 4;
#pragma unroll
        for (int i = 0; i < 4; i++) {
            const int c = tid + (i << 8);
            const int row = c >> 3, seg = c & 7;
            const uint32_t w4 = (uint32_t)(row * AT_P + seg * 4) * 4;
            const uint32_t goff = nbase + ((r0 + row) << 5) + (seg << 2);
            cpasync16(qstb + w4, g_qhi32 + goff);
            cpasync16(qstb + AT_SKL * 4 + w4, g_qlo32 + goff);
        }
    }
    CP_COMMIT();
    // also kick off tb=0 tiles into stage 0 right away (tb=0 always causal)
    at_issue(sb, 0, nbase, 0, true, tid);
    CP_COMMIT();
    CP_WAIT(1);  // Q group done
    __syncthreads();

    // extract Q fragments from stage-1 region
    uint32_t qhf[4][4], qlf[4][4];
    {
        const uint32_t* sQh = sm + AT_STW;
        const uint32_t* sQl = sm + AT_STW + AT_SKL;
#pragma unroll
        for (int kc = 0; kc < 4; kc++) {
            int b0 = (wr + gid) * AT_P + (kc << 3) + tig;
            int b1 = (wr + gid + 8) * AT_P + (kc << 3) + tig;
            qhf[kc][0] = sQh[b0]; qhf[kc][1] = sQh[b1];
            qhf[kc][2] = sQh[b0 + 4]; qhf[kc][3] = sQh[b1 + 4];
            qlf[kc][0] = sQl[b0]; qlf[kc][1] = sQl[b1];
            qlf[kc][2] = sQl[b0 + 4]; qlf[kc][3] = sQl[b1 + 4];
        }
    }
    __syncthreads();  // all warps done reading Q staging before tb=1 overwrites it

    float m0 = -1e30f, m1 = -1e30f, l0 = 0.f, l1 = 0.f;
    float oacc[8][4];
#pragma unroll
    for (int j = 0; j < 8; j++)
#pragma unroll
        for (int e = 0; e < 4; e++) oacc[j][e] = 0.f;

    const int row0 = r0 + wr + gid, row1 = row0 + 8;

    for (int tb = 0; tb < 8; tb++) {
        const int t0 = tb << 7;
        const bool causal = (tb <= rb);
        if (tb + 1 < 8) {
            at_issue(sb, (tb + 1) & 1, nbase, (tb + 1) << 7, (tb + 1) <= rb, tid);
            CP_COMMIT();
            CP_WAIT(1);
        } else {
            CP_WAIT(0);
        }
        __syncthreads();
        const uint32_t stb = sb + (tb & 1) * (AT_STW * 4);

        // ---- S = Q K^T (split bf16, 3 passes; K frags via ldmatrix.x4) ----
        float sacc[16][4];
#pragma unroll
        for (int j = 0; j < 16; j++)
#pragma unroll
            for (int e = 0; e < 4; e++) sacc[j][e] = 0.f;
#pragma unroll
        for (int j = 0; j < 16; j++) {
#pragma unroll
            for (int kc = 0; kc < 4; kc++) {
                uint32_t kf[4];
                ldm_x4(kf, stb + (kfl + j * (8 * AT_P) + (kc << 3)) * 4);
                mma16816(sacc[j], qhf[kc], kf);
                mma16816(sacc[j], qlf[kc], kf);
                mma16816(sacc[j], qhf[kc], kf + 2);
            }
        }

        // ---- heatmap (raw scores) ----
        {
            float* h0p = heat + ((size_t)n << 20) + ((size_t)row0 << 10) + t0 + (tig << 1);
            float* h1p = heat + ((size_t)n << 20) + ((size_t)row1 << 10) + t0 + (tig << 1);
#pragma unroll
            for (int j = 0; j < 16; j++) {
                *(float2*)(h0p + (j << 3)) = make_float2(sacc[j][0], sacc[j][1]);
                *(float2*)(h1p + (j << 3)) = make_float2(sacc[j][2], sacc[j][3]);
            }
        }

        if (causal) {
            if (tb == rb) {
#pragma unroll
                for (int j = 0; j < 16; j++) {
                    const int c0 = t0 + (j << 3) + (tig << 1);
                    if (c0 > row0) sacc[j][0] = -1e30f;
                    if (c0 + 1 > row0) sacc[j][1] = -1e30f;
                    if (c0 > row1) sacc[j][2] = -1e30f;
                    if (c0 + 1 > row1) sacc[j][3] = -1e30f;
                }
            }

            float vm0 = -1e30f, vm1 = -1e30f;
#pragma unroll
            for (int j = 0; j < 16; j++) {
                vm0 = fmaxf(vm0, fmaxf(sacc[j][0], sacc[j][1]));
                vm1 = fmaxf(vm1, fmaxf(sacc[j][2], sacc[j][3]));
            }
            vm0 = fmaxf(vm0, __shfl_xor_sync(0xffffffffu, vm0, 1));
            vm0 = fmaxf(vm0, __shfl_xor_sync(0xffffffffu, vm0, 2));
            vm1 = fmaxf(vm1, __shfl_xor_sync(0xffffffffu, vm1, 1));
            vm1 = fmaxf(vm1, __shfl_xor_sync(0xffffffffu, vm1, 2));
            const float mn0 = fmaxf(m0, vm0), mn1 = fmaxf(m1, vm1);
            const float sc0 = __expf(m0 - mn0), sc1 = __expf(m1 - mn1);
            m0 = mn0; m1 = mn1;
            float rs0 = 0.f, rs1 = 0.f;
#pragma unroll
            for (int j = 0; j < 16; j++) {
                sacc[j][0] = __expf(sacc[j][0] - mn0);
                sacc[j][1] = __expf(sacc[j][1] - mn0);
                sacc[j][2] = __expf(sacc[j][2] - mn1);
                sacc[j][3] = __expf(sacc[j][3] - mn1);
                rs0 += sacc[j][0] + sacc[j][1];
                rs1 += sacc[j][2] + sacc[j][3];
            }
            rs0 += __shfl_xor_sync(0xffffffffu, rs0, 1);
            rs0 += __shfl_xor_sync(0xffffffffu, rs0, 2);
            rs1 += __shfl_xor_sync(0xffffffffu, rs1, 1);
            rs1 += __shfl_xor_sync(0xffffffffu, rs1, 2);
            l0 = l0 * sc0 + rs0;
            l1 = l1 * sc1 + rs1;
#pragma unroll
            for (int j = 0; j < 8; j++) {
                oacc[j][0] *= sc0; oacc[j][1] *= sc0;
                oacc[j][2] *= sc1; oacc[j][3] *= sc1;
            }

            // ---- O += P V (V frags via ldmatrix.x4.trans on untransposed V) ----
#pragma unroll
            for (int kt = 0; kt < 8; kt++) {
                uint32_t ph[4], pl[4];
                split2(sacc[2 * kt][0], sacc[2 * kt][1], ph[0], pl[0]);
                split2(sacc[2 * kt][2], sacc[2 * kt][3], ph[1], pl[1]);
                split2(sacc[2 * kt + 1][0], sacc[2 * kt + 1][1], ph[2], pl[2]);
                split2(sacc[2 * kt + 1][2], sacc[2 * kt + 1][3], ph[3], pl[3]);
#pragma unroll
                for (int j = 0; j < 8; j++) {
                    uint32_t vf[4];
                    ldm_x4_t(vf, stb + (vfl + kt * (16 * AT_P) + (j << 2)) * 4);
                    mma16816(oacc[j], ph, vf);
                    mma16816(oacc[j], pl, vf);
                    mma16816(oacc[j], ph, vf + 2);
                }
            }
        }
        __syncthreads();  // all warps done with this stage before it is refilled
    }

    const float i0 = 1.0f / l0, i1 = 1.0f / l1;
    const uint32_t wb0 = ((bb << 10) + row0) * 256 + (hh << 5) + tig;
    const uint32_t wb1 = ((bb << 10) + row1) * 256 + (hh << 5) + tig;
#pragma unroll
    for (int j = 0; j < 8; j++) {
        uint32_t hw, lw;
        split2(oacc[j][0] * i0, oacc[j][1] * i0, hw, lw);
        g_wvhi32[wb0 + (j << 2)] = hw;
        g_wvlo32[wb0 + (j << 2)] = lw;
        split2(oacc[j][2] * i1, oacc[j][3] * i1, hw, lw);
        g_wvhi32[wb1 + (j << 2)] = hw;
        g_wvlo32[wb1 + (j << 2)] = lw;
    }
}

// ---------------- launch ------------------------------------------------------
extern "C" void kernel_launch(void* const* d_in, const int* in_sizes, int n_in,
                              void* d_out, int out_size) {
    const float* x  = (const float*)d_in[0];
    const float* Wq = (const float*)d_in[1];
    const float* bq = (const float*)d_in[2];
    const float* Wk = (const float*)d_in[3];
    const float* bk = (const float*)d_in[4];
    const float* Wv = (const float*)d_in[5];
    const float* bv = (const float*)d_in[6];
    const float* Wo = (const float*)d_in[7];
    const float* bo = (const float*)d_in[8];

    float* out = (float*)d_out;
    float* heat = out + (size_t)8 * 1024 * 512;

    cudaFuncSetAttribute(attn_kernel, cudaFuncAttributeMaxDynamicSharedMemorySize,
                         AT_SMEM_BYTES);
    cudaFuncSetAttribute(tgemm, cudaFuncAttributeMaxDynamicSharedMemorySize,
                         TG_SMEM_BYTES);

    conv_x<<<4096, 256>>>(x);
    conv_wt<<<dim3(16, 16, 4), dim3(32, 32)>>>(Wq, Wk, Wv, Wo);

    tgemm<<<dim3(4, 64, 3), 256, TG_SMEM_BYTES>>>(0, 0, bq, bk, bv, nullptr, 1);
    attn_kernel<<<dim3(8, 64), 256, AT_SMEM_BYTES>>>(heat);
    tgemm<<<dim3(4, 64, 1), 256, TG_SMEM_BYTES>>>(1, 3, bo, nullptr, nullptr, out, 0);
}

// round 8
// speedup vs baseline: 2.7269x; 1.1076x over previous
#include <cuda_runtime.h>
#include <cuda_bf16.h>
#include <cstdint>
#include <cstddef>

// B=8, S=1024, D=512, H=8, qdim=vdim=64, n=H*B=64
// d_out = out [8,1024,512] ++ heatmap [64,1024,1024]

// ---------------- scratch globals (bf16 pairs stored as u32 words) ------------
__device__ uint32_t g_qhi32[64ull * 1024 * 32], g_qlo32[64ull * 1024 * 32];
__device__ uint32_t g_khi32[64ull * 1024 * 32], g_klo32[64ull * 1024 * 32];
__device__ uint32_t g_vhi32[64ull * 1024 * 32], g_vlo32[64ull * 1024 * 32];
__device__ uint32_t g_wvhi32[8192ull * 256], g_wvlo32[8192ull * 256];
__device__ __nv_bfloat16 g_xhi[8192ull * 512], g_xlo[8192ull * 512];
__device__ __nv_bfloat16 g_wth[4][512 * 512], g_wtl[4][512 * 512];

// ---------------- helpers ------------------------------------------------------
__device__ __forceinline__ void mma16816(float* c, const uint32_t* a, const uint32_t* b) {
    asm volatile(
        "mma.sync.aligned.m16n8k16.row.col.f32.bf16.bf16.f32 "
        "{%0,%1,%2,%3}, {%4,%5,%6,%7}, {%8,%9}, {%0,%1,%2,%3};"
        : "+f"(c[0]), "+f"(c[1]), "+f"(c[2]), "+f"(c[3])
        : "r"(a[0]), "r"(a[1]), "r"(a[2]), "r"(a[3]), "r"(b[0]), "r"(b[1]));
}
__device__ __forceinline__ uint32_t packbf(float lo, float hi) {
    uint32_t r;
    asm("cvt.rn.bf16x2.f32 %0, %1, %2;" : "=r"(r) : "f"(hi), "f"(lo));
    return r;
}
__device__ __forceinline__ void split2(float a, float b, uint32_t& hw, uint32_t& lw) {
    uint32_t h = packbf(a, b);
    __nv_bfloat162 h2 = *reinterpret_cast<__nv_bfloat162*>(&h);
    float ra = a - __low2float(h2);
    float rb = b - __high2float(h2);
    hw = h;
    lw = packbf(ra, rb);
}
__device__ __forceinline__ uint32_t smem_u32(const void* p) {
    uint32_t a;
    asm("{ .reg .u64 t; cvta.to.shared.u64 t, %1; cvt.u32.u64 %0, t; }" : "=r"(a) : "l"(p));
    return a;
}
__device__ __forceinline__ void cpasync16(uint32_t saddr, const void* gptr) {
    asm volatile("cp.async.ca.shared.global [%0], [%1], 16;" :: "r"(saddr), "l"(gptr));
}
#define CP_COMMIT() asm volatile("cp.async.commit_group;" ::: "memory")
#define CP_WAIT(n) asm volatile("cp.async.wait_group %0;" :: "n"(n) : "memory")
__device__ __forceinline__ void ldm_x4(uint32_t* r, uint32_t addr) {
    asm volatile("ldmatrix.sync.aligned.m8n8.x4.shared.b16 {%0,%1,%2,%3}, [%4];"
                 : "=r"(r[0]), "=r"(r[1]), "=r"(r[2]), "=r"(r[3]) : "r"(addr));
}
__device__ __forceinline__ void ldm_x4_t(uint32_t* r, uint32_t addr) {
    asm volatile("ldmatrix.sync.aligned.m8n8.x4.trans.shared.b16 {%0,%1,%2,%3}, [%4];"
                 : "=r"(r[0]), "=r"(r[1]), "=r"(r[2]), "=r"(r[3]) : "r"(addr));
}

// ---------------- conversion kernels ------------------------------------------
__global__ __launch_bounds__(256) void conv_x(const float* __restrict__ X) {
    size_t i = ((size_t)blockIdx.x * 256 + threadIdx.x) * 4;
    float4 v = *(const float4*)(X + i);
    uint32_t h0, l0, h1, l1;
    split2(v.x, v.y, h0, l0);
    split2(v.z, v.w, h1, l1);
    *(uint32_t*)(g_xhi + i) = h0;
    *(uint32_t*)(g_xhi + i + 2) = h1;
    *(uint32_t*)(g_xlo + i) = l0;
    *(uint32_t*)(g_xlo + i + 2) = l1;
}

__global__ void conv_wt(const float* __restrict__ W0, const float* __restrict__ W1,
                        const float* __restrict__ W2, const float* __restrict__ W3) {
    __shared__ float t[32][33];
    const int widx = blockIdx.z;
    const float* W = (widx == 0) ? W0 : (widx == 1) ? W1 : (widx == 2) ? W2 : W3;
    int k = blockIdx.y * 32 + threadIdx.y;
    int n = blockIdx.x * 32 + threadIdx.x;
    t[threadIdx.y][threadIdx.x] = W[(size_t)k * 512 + n];
    __syncthreads();
    int n2 = blockIdx.x * 32 + threadIdx.y;
    int k2 = blockIdx.y * 32 + threadIdx.x;
    float v = t[threadIdx.x][threadIdx.y];
    __nv_bfloat16 h = __float2bfloat16_rn(v);
    g_wth[widx][(size_t)n2 * 512 + k2] = h;
    g_wtl[widx][(size_t)n2 * 512 + k2] = __float2bfloat16_rn(v - __bfloat162float(h));
}

// ---------------- HMMA split-bf16 GEMM (cp.async + ldmatrix, 2 CTA/SM) --------
#define TPAD 40
#define TG_ARR (128 * TPAD)
#define TG_STAGE (4 * TG_ARR)
#define TG_SMEM_BYTES (2 * TG_STAGE * 2)

__device__ __forceinline__ void tg_issue(uint32_t sb, int stage,
                                         const __nv_bfloat16* __restrict__ Ah,
                                         const __nv_bfloat16* __restrict__ Al,
                                         const __nv_bfloat16* __restrict__ Bh,
                                         const __nv_bfloat16* __restrict__ Bl,
                                         int m0, int n0, int k0, int tid) {
    const int row = tid >> 1, half = tid & 1;
    const uint32_t base = sb + stage * (TG_STAGE * 2);
    const uint32_t doff = (uint32_t)(row * TPAD + half * 16) * 2;
    const __nv_bfloat16* srcs[4] = {
        Ah + (size_t)(m0 + row) * 512 + k0 + half * 16,
        Al + (size_t)(m0 + row) * 512 + k0 + half * 16,
        Bh + (size_t)(n0 + row) * 512 + k0 + half * 16,
        Bl + (size_t)(n0 + row) * 512 + k0 + half * 16};
#pragma unroll
    for (int a = 0; a < 4; a++) {
        uint32_t d = base + a * (TG_ARR * 2) + doff;
        cpasync16(d, srcs[a]);
        cpasync16(d + 16, (const char*)srcs[a] + 16);
    }
}

__global__ __launch_bounds__(256, 2) void tgemm(int asel, int widx0,
                                                const float* __restrict__ bz0,
                                                const float* __restrict__ bz1,
                                                const float* __restrict__ bz2,
                                                float* __restrict__ outp, int mode0) {
    extern __shared__ __nv_bfloat16 smem[];
    const uint32_t sb = smem_u32(smem);

    const int z = blockIdx.z;
    const int widx = widx0 + z;
    const int mode = mode0 ? mode0 + z : 0;
    const float* bias = (z == 0) ? bz0 : (z == 1) ? bz1 : bz2;

    const int tid = threadIdx.x;
    const int wid = tid >> 5, lane = tid & 31;
    const int gid = lane >> 2, tig = lane & 3;
    const int wm0 = (wid >> 2) << 6;
    const int wn0 = (wid & 3) << 5;
    const int n0 = blockIdx.x << 7, m0 = blockIdx.y << 7;

    // per-lane ldmatrix offsets (bf16-element units within a stage)
    const int lrow = lane & 7;
    const uint32_t aoff = (uint32_t)(wm0 + ((lane >> 3) & 1) * 8 + lrow) * TPAD +
                          (lane >> 4) * 8;
    const uint32_t boff = (uint32_t)(2 + (lane >> 4)) * TG_ARR +
                          (uint32_t)(wn0 + lrow) * TPAD + ((lane >> 3) & 1) * 8;

    const __nv_bfloat16* Ah = asel ? (const __nv_bfloat16*)g_wvhi32 : g_xhi;
    const __nv_bfloat16* Al = asel ? (const __nv_bfloat16*)g_wvlo32 : g_xlo;
    const __nv_bfloat16* Bh = g_wth[widx];
    const __nv_bfloat16* Bl = g_wtl[widx];

    float acc[4][4][4];
#pragma unroll
    for (int i = 0; i < 4; i++)
#pragma unroll
        for (int j = 0; j < 4; j++)
#pragma unroll
            for (int e = 0; e < 4; e++) acc[i][j][e] = 0.f;

    tg_issue(sb, 0, Ah, Al, Bh, Bl, m0, n0, 0, tid);
    CP_COMMIT();

    for (int c = 0; c < 16; c++) {
        __syncthreads();
        if (c + 1 < 16) {
            tg_issue(sb, (c + 1) & 1, Ah, Al, Bh, Bl, m0, n0, (c + 1) << 5, tid);
            CP_COMMIT();
            CP_WAIT(1);
        } else {
            CP_WAIT(0);
        }
        __syncthreads();

        const uint32_t stb = sb + (c & 1) * (TG_STAGE * 2);
#pragma unroll
        for (int ks = 0; ks < 32; ks += 16) {
            uint32_t ah[4][4], al[4][4], bhl[4][4];
#pragma unroll
            for (int i = 0; i < 4; i++) {
                ldm_x4(ah[i], stb + (aoff + i * (16 * TPAD) + ks) * 2);
                ldm_x4(al[i], stb + (TG_ARR + aoff + i * (16 * TPAD) + ks) * 2);
            }
#pragma unroll
            for (int j = 0; j < 4; j++)
                ldm_x4(bhl[j], stb + (boff + j * (8 * TPAD) + ks) * 2);
#pragma unroll
            for (int i = 0; i < 4; i++)
#pragma unroll
                for (int j = 0; j < 4; j++) {
                    mma16816(acc[i][j], ah[i], bhl[j]);      // hi*hi
                    mma16816(acc[i][j], ah[i], bhl[j] + 2);  // hi*lo
                    mma16816(acc[i][j], al[i], bhl[j]);      // lo*hi
                }
        }
    }

    uint32_t* qh = (mode == 1) ? g_qhi32 : (mode == 2) ? g_khi32 : g_vhi32;
    uint32_t* ql = (mode == 1) ? g_qlo32 : (mode == 2) ? g_klo32 : g_vlo32;
#pragma unroll
    for (int i = 0; i < 4; i++) {
        const int r = m0 + wm0 + (i << 4) + gid;
#pragma unroll
        for (int j = 0; j < 4; j++) {
            const int col = n0 + wn0 + (j << 3) + (tig << 1);
            const float b0 = bias[col], b1 = bias[col + 1];
            float w00 = acc[i][j][0] + b0, w01 = acc[i][j][1] + b1;
            float w10 = acc[i][j][2] + b0, w11 = acc[i][j][3] + b1;
            if (mode == 0) {
                *(float2*)(outp + (size_t)r * 512 + col) = make_float2(w00, w01);
                *(float2*)(outp + (size_t)(r + 8) * 512 + col) = make_float2(w10, w11);
            } else {
                const int h = col >> 6, d = col & 63;
                const int bb = r >> 10, s = r & 1023;
                size_t w = (((size_t)(h * 8 + bb)) << 15) + ((size_t)s << 5) + (d >> 1);
                uint32_t hw, lw;
                split2(w00, w01, hw, lw);
                qh[w] = hw; ql[w] = lw;
                split2(w10, w11, hw, lw);
                qh[w + 256] = hw; ql[w + 256] = lw;
            }
        }
    }
}

// ---------------- tensorized fused attention + heatmap ------------------------
#define AT_P 36
#define AT_SKL 4608
#define AT_SVH 9216
#define AT_SVL 13824
#define AT_STW 18432
#define AT_SMEM_BYTES (2 * AT_STW * 4)

__device__ __forceinline__ void at_issue(uint32_t sb, int stage, uint32_t nbase,
                                         int t0, bool withV, int tid) {
    const uint32_t stb = sb + stage * (AT_STW * 4);
#pragma unroll
    for (int i = 0; i < 4; i++) {
        const int c = tid + (i << 8);
        const int row = c >> 3, seg = c & 7;
        const uint32_t w4 = (uint32_t)(row * AT_P + seg * 4) * 4;
        const uint32_t goff = nbase + ((t0 + row) << 5) + (seg << 2);
        cpasync16(stb + w4, g_khi32 + goff);
        cpasync16(stb + AT_SKL * 4 + w4, g_klo32 + goff);
        if (withV) {
            cpasync16(stb + AT_SVH * 4 + w4, g_vhi32 + goff);
            cpasync16(stb + AT_SVL * 4 + w4, g_vlo32 + goff);
        }
    }
}

__global__ __launch_bounds__(256) void attn_kernel(float* __restrict__ heat) {
    extern __shared__ uint32_t sm[];
    const uint32_t sb = smem_u32(sm);

    const int tid = threadIdx.x;
    const int wid = tid >> 5, lane = tid & 31;
    const int gid = lane >> 2, tig = lane & 3;
    const int rb = blockIdx.x, n = blockIdx.y;
    const int r0 = rb << 7, wr = wid << 4;
    const int hh = n >> 3, bb = n & 7;
    const uint32_t nbase = n << 15;

    const int sel = lane >> 3, lrow = lane & 7;
    const uint32_t kfl = ((sel & 2) ? AT_SKL : 0) + lrow * AT_P + ((sel & 1) << 2);
    const uint32_t vfl = ((sel & 2) ? AT_SVL : AT_SVH) + (((sel & 1) << 3) + lrow) * AT_P;

    {
        const uint32_t qstb = sb + AT_STW * 4;
#pragma unroll
        for (int i = 0; i < 4; i++) {
            const int c = tid + (i << 8);
            const int row = c >> 3, seg = c & 7;
            const uint32_t w4 = (uint32_t)(row * AT_P + seg * 4) * 4;
            const uint32_t goff = nbase + ((r0 + row) << 5) + (seg << 2);
            cpasync16(qstb + w4, g_qhi32 + goff);
            cpasync16(qstb + AT_SKL * 4 + w4, g_qlo32 + goff);
        }
    }
    CP_COMMIT();
    at_issue(sb, 0, nbase, 0, true, tid);
    CP_COMMIT();
    CP_WAIT(1);
    __syncthreads();

    uint32_t qhf[4][4], qlf[4][4];
    {
        const uint32_t* sQh = sm + AT_STW;
        const uint32_t* sQl = sm + AT_STW + AT_SKL;
#pragma unroll
        for (int kc = 0; kc < 4; kc++) {
            int b0 = (wr + gid) * AT_P + (kc << 3) + tig;
            int b1 = (wr + gid + 8) * AT_P + (kc << 3) + tig;
            qhf[kc][0] = sQh[b0]; qhf[kc][1] = sQh[b1];
            qhf[kc][2] = sQh[b0 + 4]; qhf[kc][3] = sQh[b1 + 4];
            qlf[kc][0] = sQl[b0]; qlf[kc][1] = sQl[b1];
            qlf[kc][2] = sQl[b0 + 4]; qlf[kc][3] = sQl[b1 + 4];
        }
    }
    __syncthreads();

    float m0 = -1e30f, m1 = -1e30f, l0 = 0.f, l1 = 0.f;
    float oacc[8][4];
#pragma unroll
    for (int j = 0; j < 8; j++)
#pragma unroll
        for (int e = 0; e < 4; e++) oacc[j][e] = 0.f;

    const int row0 = r0 + wr + gid, row1 = row0 + 8;

    for (int tb = 0; tb < 8; tb++) {
        const int t0 = tb << 7;
        const bool causal = (tb <= rb);
        if (tb + 1 < 8) {
            at_issue(sb, (tb + 1) & 1, nbase, (tb + 1) << 7, (tb + 1) <= rb, tid);
            CP_COMMIT();
            CP_WAIT(1);
        } else {
            CP_WAIT(0);
        }
        __syncthreads();
        const uint32_t stb = sb + (tb & 1) * (AT_STW * 4);

        float sacc[16][4];
#pragma unroll
        for (int j = 0; j < 16; j++)
#pragma unroll
            for (int e = 0; e < 4; e++) sacc[j][e] = 0.f;
#pragma unroll
        for (int j = 0; j < 16; j++) {
#pragma unroll
            for (int kc = 0; kc < 4; kc++) {
                uint32_t kf[4];
                ldm_x4(kf, stb + (kfl + j * (8 * AT_P) + (kc << 3)) * 4);
                mma16816(sacc[j], qhf[kc], kf);
                mma16816(sacc[j], qlf[kc], kf);
                mma16816(sacc[j], qhf[kc], kf + 2);
            }
        }

        {
            float* h0p = heat + ((size_t)n << 20) + ((size_t)row0 << 10) + t0 + (tig << 1);
            float* h1p = heat + ((size_t)n << 20) + ((size_t)row1 << 10) + t0 + (tig << 1);
#pragma unroll
            for (int j = 0; j < 16; j++) {
                *(float2*)(h0p + (j << 3)) = make_float2(sacc[j][0], sacc[j][1]);
                *(float2*)(h1p + (j << 3)) = make_float2(sacc[j][2], sacc[j][3]);
            }
        }

        if (causal) {
            if (tb == rb) {
#pragma unroll
                for (int j = 0; j < 16; j++) {
                    const int c0 = t0 + (j << 3) + (tig << 1);
                    if (c0 > row0) sacc[j][0] = -1e30f;
                    if (c0 + 1 > row0) sacc[j][1] = -1e30f;
                    if (c0 > row1) sacc[j][2] = -1e30f;
                    if (c0 + 1 > row1) sacc[j][3] = -1e30f;
                }
            }

            float vm0 = -1e30f, vm1 = -1e30f;
#pragma unroll
            for (int j = 0; j < 16; j++) {
                vm0 = fmaxf(vm0, fmaxf(sacc[j][0], sacc[j][1]));
                vm1 = fmaxf(vm1, fmaxf(sacc[j][2], sacc[j][3]));
            }
            vm0 = fmaxf(vm0, __shfl_xor_sync(0xffffffffu, vm0, 1));
            vm0 = fmaxf(vm0, __shfl_xor_sync(0xffffffffu, vm0, 2));
            vm1 = fmaxf(vm1, __shfl_xor_sync(0xffffffffu, vm1, 1));
            vm1 = fmaxf(vm1, __shfl_xor_sync(0xffffffffu, vm1, 2));
            const float mn0 = fmaxf(m0, vm0), mn1 = fmaxf(m1, vm1);
            const float sc0 = __expf(m0 - mn0), sc1 = __expf(m1 - mn1);
            m0 = mn0; m1 = mn1;
            float rs0 = 0.f, rs1 = 0.f;
#pragma unroll
            for (int j = 0; j < 16; j++) {
                sacc[j][0] = __expf(sacc[j][0] - mn0);
                sacc[j][1] = __expf(sacc[j][1] - mn0);
                sacc[j][2] = __expf(sacc[j][2] - mn1);
                sacc[j][3] = __expf(sacc[j][3] - mn1);
                rs0 += sacc[j][0] + sacc[j][1];
                rs1 += sacc[j][2] + sacc[j][3];
            }
            rs0 += __shfl_xor_sync(0xffffffffu, rs0, 1);
            rs0 += __shfl_xor_sync(0xffffffffu, rs0, 2);
            rs1 += __shfl_xor_sync(0xffffffffu, rs1, 1);
            rs1 += __shfl_xor_sync(0xffffffffu, rs1, 2);
            l0 = l0 * sc0 + rs0;
            l1 = l1 * sc1 + rs1;
#pragma unroll
            for (int j = 0; j < 8; j++) {
                oacc[j][0] *= sc0; oacc[j][1] *= sc0;
                oacc[j][2] *= sc1; oacc[j][3] *= sc1;
            }

#pragma unroll
            for (int kt = 0; kt < 8; kt++) {
                uint32_t ph[4], pl[4];
                split2(sacc[2 * kt][0], sacc[2 * kt][1], ph[0], pl[0]);
                split2(sacc[2 * kt][2], sacc[2 * kt][3], ph[1], pl[1]);
                split2(sacc[2 * kt + 1][0], sacc[2 * kt + 1][1], ph[2], pl[2]);
                split2(sacc[2 * kt + 1][2], sacc[2 * kt + 1][3], ph[3], pl[3]);
#pragma unroll
                for (int j = 0; j < 8; j++) {
                    uint32_t vf[4];
                    ldm_x4_t(vf, stb + (vfl + kt * (16 * AT_P) + (j << 2)) * 4);
                    mma16816(oacc[j], ph, vf);
                    mma16816(oacc[j], pl, vf);
                    mma16816(oacc[j], ph, vf + 2);
                }
            }
        }
        __syncthreads();
    }

    const float i0 = 1.0f / l0, i1 = 1.0f / l1;
    const uint32_t wb0 = ((bb << 10) + row0) * 256 + (hh << 5) + tig;
    const uint32_t wb1 = ((bb << 10) + row1) * 256 + (hh << 5) + tig;
#pragma unroll
    for (int j = 0; j < 8; j++) {
        uint32_t hw, lw;
        split2(oacc[j][0] * i0, oacc[j][1] * i0, hw, lw);
        g_wvhi32[wb0 + (j << 2)] = hw;
        g_wvlo32[wb0 + (j << 2)] = lw;
        split2(oacc[j][2] * i1, oacc[j][3] * i1, hw, lw);
        g_wvhi32[wb1 + (j << 2)] = hw;
        g_wvlo32[wb1 + (j << 2)] = lw;
    }
}

// ---------------- launch ------------------------------------------------------
extern "C" void kernel_launch(void* const* d_in, const int* in_sizes, int n_in,
                              void* d_out, int out_size) {
    const float* x  = (const float*)d_in[0];
    const float* Wq = (const float*)d_in[1];
    const float* bq = (const float*)d_in[2];
    const float* Wk = (const float*)d_in[3];
    const float* bk = (const float*)d_in[4];
    const float* Wv = (const float*)d_in[5];
    const float* bv = (const float*)d_in[6];
    const float* Wo = (const float*)d_in[7];
    const float* bo = (const float*)d_in[8];

    float* out = (float*)d_out;
    float* heat = out + (size_t)8 * 1024 * 512;

    cudaFuncSetAttribute(attn_kernel, cudaFuncAttributeMaxDynamicSharedMemorySize,
                         AT_SMEM_BYTES);
    cudaFuncSetAttribute(tgemm, cudaFuncAttributeMaxDynamicSharedMemorySize,
                         TG_SMEM_BYTES);

    conv_x<<<4096, 256>>>(x);
    conv_wt<<<dim3(16, 16, 4), dim3(32, 32)>>>(Wq, Wk, Wv, Wo);

    tgemm<<<dim3(4, 64, 3), 256, TG_SMEM_BYTES>>>(0, 0, bq, bk, bv, nullptr, 1);
    attn_kernel<<<dim3(8, 64), 256, AT_SMEM_BYTES>>>(heat);
    tgemm<<<dim3(4, 64, 1), 256, TG_SMEM_BYTES>>>(1, 3, bo, nullptr, nullptr, out, 0);
}

// round 10
// speedup vs baseline: 2.7282x; 1.0004x over previous
#include <cuda_runtime.h>
#include <cuda_bf16.h>
#include <cstdint>
#include <cstddef>

// B=8, S=1024, D=512, H=8, qdim=vdim=64, n=H*B=64
// d_out = out [8,1024,512] ++ heatmap [64,1024,1024]

// ---------------- scratch globals (bf16 pairs stored as u32 words) ------------
__device__ uint32_t g_qhi32[64ull * 1024 * 32], g_qlo32[64ull * 1024 * 32];
__device__ uint32_t g_khi32[64ull * 1024 * 32], g_klo32[64ull * 1024 * 32];
__device__ uint32_t g_vhi32[64ull * 1024 * 32], g_vlo32[64ull * 1024 * 32];
__device__ uint32_t g_wvhi32[8192ull * 256], g_wvlo32[8192ull * 256];
__device__ __nv_bfloat16 g_xhi[8192ull * 512], g_xlo[8192ull * 512];
__device__ __nv_bfloat16 g_wth[4][512 * 512], g_wtl[4][512 * 512];

// ---------------- helpers ------------------------------------------------------
__device__ __forceinline__ void mma16816(float* c, const uint32_t* a, const uint32_t* b) {
    asm volatile(
        "mma.sync.aligned.m16n8k16.row.col.f32.bf16.bf16.f32 "
        "{%0,%1,%2,%3}, {%4,%5,%6,%7}, {%8,%9}, {%0,%1,%2,%3};"
        : "+f"(c[0]), "+f"(c[1]), "+f"(c[2]), "+f"(c[3])
        : "r"(a[0]), "r"(a[1]), "r"(a[2]), "r"(a[3]), "r"(b[0]), "r"(b[1]));
}
__device__ __forceinline__ uint32_t packbf(float lo, float hi) {
    uint32_t r;
    asm("cvt.rn.bf16x2.f32 %0, %1, %2;" : "=r"(r) : "f"(hi), "f"(lo));
    return r;
}
__device__ __forceinline__ void split2(float a, float b, uint32_t& hw, uint32_t& lw) {
    uint32_t h = packbf(a, b);
    __nv_bfloat162 h2 = *reinterpret_cast<__nv_bfloat162*>(&h);
    float ra = a - __low2float(h2);
    float rb = b - __high2float(h2);
    hw = h;
    lw = packbf(ra, rb);
}
__device__ __forceinline__ uint32_t smem_u32(const void* p) {
    uint32_t a;
    asm("{ .reg .u64 t; cvta.to.shared.u64 t, %1; cvt.u32.u64 %0, t; }" : "=r"(a) : "l"(p));
    return a;
}
__device__ __forceinline__ void cpasync16(uint32_t saddr, const void* gptr) {
    asm volatile("cp.async.ca.shared.global [%0], [%1], 16;" :: "r"(saddr), "l"(gptr));
}
#define CP_COMMIT() asm volatile("cp.async.commit_group;" ::: "memory")
#define CP_WAIT(n) asm volatile("cp.async.wait_group %0;" :: "n"(n) : "memory")
__device__ __forceinline__ void ldm_x4(uint32_t* r, uint32_t addr) {
    asm volatile("ldmatrix.sync.aligned.m8n8.x4.shared.b16 {%0,%1,%2,%3}, [%4];"
                 : "=r"(r[0]), "=r"(r[1]), "=r"(r[2]), "=r"(r[3]) : "r"(addr));
}
__device__ __forceinline__ void ldm_x4_t(uint32_t* r, uint32_t addr) {
    asm volatile("ldmatrix.sync.aligned.m8n8.x4.trans.shared.b16 {%0,%1,%2,%3}, [%4];"
                 : "=r"(r[0]), "=r"(r[1]), "=r"(r[2]), "=r"(r[3]) : "r"(addr));
}

// ---------------- conversion kernels ------------------------------------------
__global__ __launch_bounds__(256) void conv_x(const float* __restrict__ X) {
    size_t i = ((size_t)blockIdx.x * 256 + threadIdx.x) * 4;
    float4 v = *(const float4*)(X + i);
    uint32_t h0, l0, h1, l1;
    split2(v.x, v.y, h0, l0);
    split2(v.z, v.w, h1, l1);
    *(uint32_t*)(g_xhi + i) = h0;
    *(uint32_t*)(g_xhi + i + 2) = h1;
    *(uint32_t*)(g_xlo + i) = l0;
    *(uint32_t*)(g_xlo + i + 2) = l1;
}

__global__ void conv_wt(const float* __restrict__ W0, const float* __restrict__ W1,
                        const float* __restrict__ W2, const float* __restrict__ W3) {
    __shared__ float t[32][33];
    const int widx = blockIdx.z;
    const float* W = (widx == 0) ? W0 : (widx == 1) ? W1 : (widx == 2) ? W2 : W3;
    int k = blockIdx.y * 32 + threadIdx.y;
    int n = blockIdx.x * 32 + threadIdx.x;
    t[threadIdx.y][threadIdx.x] = W[(size_t)k * 512 + n];
    __syncthreads();
    int n2 = blockIdx.x * 32 + threadIdx.y;
    int k2 = blockIdx.y * 32 + threadIdx.x;
    float v = t[threadIdx.x][threadIdx.y];
    __nv_bfloat16 h = __float2bfloat16_rn(v);
    g_wth[widx][(size_t)n2 * 512 + k2] = h;
    g_wtl[widx][(size_t)n2 * 512 + k2] = __float2bfloat16_rn(v - __bfloat162float(h));
}

// ---------------- HMMA split-bf16 GEMM (cp.async + ldmatrix, 2 CTA/SM) --------
#define TPAD 40
#define TG_ARR (128 * TPAD)
#define TG_STAGE (4 * TG_ARR)
#define TG_SMEM_BYTES (2 * TG_STAGE * 2)

__device__ __forceinline__ void tg_issue(uint32_t sb, int stage,
                                         const __nv_bfloat16* __restrict__ Ah,
                                         const __nv_bfloat16* __restrict__ Al,
                                         const __nv_bfloat16* __restrict__ Bh,
                                         const __nv_bfloat16* __restrict__ Bl,
                                         int m0, int n0, int k0, int tid) {
    const int row = tid >> 1, half = tid & 1;
    const uint32_t base = sb + stage * (TG_STAGE * 2);
    const uint32_t doff = (uint32_t)(row * TPAD + half * 16) * 2;
    const __nv_bfloat16* srcs[4] = {
        Ah + (size_t)(m0 + row) * 512 + k0 + half * 16,
        Al + (size_t)(m0 + row) * 512 + k0 + half * 16,
        Bh + (size_t)(n0 + row) * 512 + k0 + half * 16,
        Bl + (size_t)(n0 + row) * 512 + k0 + half * 16};
#pragma unroll
    for (int a = 0; a < 4; a++) {
        uint32_t d = base + a * (TG_ARR * 2) + doff;
        cpasync16(d, srcs[a]);
        cpasync16(d + 16, (const char*)srcs[a] + 16);
    }
}

__global__ __launch_bounds__(256, 2) void tgemm(int asel, int widx0,
                                                const float* __restrict__ bz0,
                                                const float* __restrict__ bz1,
                                                const float* __restrict__ bz2,
                                                float* __restrict__ outp, int mode0) {
    extern __shared__ __nv_bfloat16 smem[];
    const uint32_t sb = smem_u32(smem);

    const int z = blockIdx.z;
    const int widx = widx0 + z;
    const int mode = mode0 ? mode0 + z : 0;
    const float* bias = (z == 0) ? bz0 : (z == 1) ? bz1 : bz2;

    const int tid = threadIdx.x;
    const int wid = tid >> 5, lane = tid & 31;
    const int gid = lane >> 2, tig = lane & 3;
    const int wm0 = (wid >> 2) << 6;
    const int wn0 = (wid & 3) << 5;
    const int n0 = blockIdx.x << 7, m0 = blockIdx.y << 7;

    const int lrow = lane & 7;
    const uint32_t aoff = (uint32_t)(wm0 + ((lane >> 3) & 1) * 8 + lrow) * TPAD +
                          (lane >> 4) * 8;
    const uint32_t boff = (uint32_t)(2 + (lane >> 4)) * TG_ARR +
                          (uint32_t)(wn0 + lrow) * TPAD + ((lane >> 3) & 1) * 8;

    const __nv_bfloat16* Ah = asel ? (const __nv_bfloat16*)g_wvhi32 : g_xhi;
    const __nv_bfloat16* Al = asel ? (const __nv_bfloat16*)g_wvlo32 : g_xlo;
    const __nv_bfloat16* Bh = g_wth[widx];
    const __nv_bfloat16* Bl = g_wtl[widx];

    float acc[4][4][4];
#pragma unroll
    for (int i = 0; i < 4; i++)
#pragma unroll
        for (int j = 0; j < 4; j++)
#pragma unroll
            for (int e = 0; e < 4; e++) acc[i][j][e] = 0.f;

    tg_issue(sb, 0, Ah, Al, Bh, Bl, m0, n0, 0, tid);
    CP_COMMIT();

    for (int c = 0; c < 16; c++) {
        __syncthreads();
        if (c + 1 < 16) {
            tg_issue(sb, (c + 1) & 1, Ah, Al, Bh, Bl, m0, n0, (c + 1) << 5, tid);
            CP_COMMIT();
            CP_WAIT(1);
        } else {
            CP_WAIT(0);
        }
        __syncthreads();

        const uint32_t stb = sb + (c & 1) * (TG_STAGE * 2);
#pragma unroll
        for (int ks = 0; ks < 32; ks += 16) {
            uint32_t ah[4][4], al[4][4], bhl[4][4];
#pragma unroll
            for (int i = 0; i < 4; i++) {
                ldm_x4(ah[i], stb + (aoff + i * (16 * TPAD) + ks) * 2);
                ldm_x4(al[i], stb + (TG_ARR + aoff + i * (16 * TPAD) + ks) * 2);
            }
#pragma unroll
            for (int j = 0; j < 4; j++)
                ldm_x4(bhl[j], stb + (boff + j * (8 * TPAD) + ks) * 2);
#pragma unroll
            for (int i = 0; i < 4; i++)
#pragma unroll
                for (int j = 0; j < 4; j++) {
                    mma16816(acc[i][j], ah[i], bhl[j]);      // hi*hi
                    mma16816(acc[i][j], ah[i], bhl[j] + 2);  // hi*lo
                    mma16816(acc[i][j], al[i], bhl[j]);      // lo*hi
                }
        }
    }

    uint32_t* qh = (mode == 1) ? g_qhi32 : (mode == 2) ? g_khi32 : g_vhi32;
    uint32_t* ql = (mode == 1) ? g_qlo32 : (mode == 2) ? g_klo32 : g_vlo32;
#pragma unroll
    for (int i = 0; i < 4; i++) {
        const int r = m0 + wm0 + (i << 4) + gid;
#pragma unroll
        for (int j = 0; j < 4; j++) {
            const int col = n0 + wn0 + (j << 3) + (tig << 1);
            const float b0 = bias[col], b1 = bias[col + 1];
            float w00 = acc[i][j][0] + b0, w01 = acc[i][j][1] + b1;
            float w10 = acc[i][j][2] + b0, w11 = acc[i][j][3] + b1;
            if (mode == 0) {
                *(float2*)(outp + (size_t)r * 512 + col) = make_float2(w00, w01);
                *(float2*)(outp + (size_t)(r + 8) * 512 + col) = make_float2(w10, w11);
            } else {
                const int h = col >> 6, d = col & 63;
                const int bb = r >> 10, s = r & 1023;
                size_t w = (((size_t)(h * 8 + bb)) << 15) + ((size_t)s << 5) + (d >> 1);
                uint32_t hw, lw;
                split2(w00, w01, hw, lw);
                qh[w] = hw; ql[w] = lw;
                split2(w10, w11, hw, lw);
                qh[w + 256] = hw; ql[w + 256] = lw;
            }
        }
    }
}

// ---------------- tensorized fused attention + heatmap ------------------------
#define AT_P 36
#define AT_SKL 4608
#define AT_SVH 9216
#define AT_SVL 13824
#define AT_STW 18432
#define AT_SMEM_BYTES (2 * AT_STW * 4)

__device__ __forceinline__ void at_issue(uint32_t sb, int stage, uint32_t nbase,
                                         int t0, bool withV, int tid) {
    const uint32_t stb = sb + stage * (AT_STW * 4);
#pragma unroll
    for (int i = 0; i < 4; i++) {
        const int c = tid + (i << 8);
        const int row = c >> 3, seg = c & 7;
        const uint32_t w4 = (uint32_t)(row * AT_P + seg * 4) * 4;
        const uint32_t goff = nbase + ((t0 + row) << 5) + (seg << 2);
        cpasync16(stb + w4, g_khi32 + goff);
        cpasync16(stb + AT_SKL * 4 + w4, g_klo32 + goff);
        if (withV) {
            cpasync16(stb + AT_SVH * 4 + w4, g_vhi32 + goff);
            cpasync16(stb + AT_SVL * 4 + w4, g_vlo32 + goff);
        }
    }
}

__global__ __launch_bounds__(256) void attn_kernel(float* __restrict__ heat) {
    extern __shared__ uint32_t sm[];
    const uint32_t sb = smem_u32(sm);

    const int tid = threadIdx.x;
    const int wid = tid >> 5, lane = tid & 31;
    const int gid = lane >> 2, tig = lane & 3;
    const int rb = blockIdx.x, n = blockIdx.y;
    const int r0 = rb << 7, wr = wid << 4;
    const int hh = n >> 3, bb = n & 7;
    const uint32_t nbase = n << 15;

    const int sel = lane >> 3, lrow = lane & 7;
    const uint32_t kfl = ((sel & 2) ? AT_SKL : 0) + lrow * AT_P + ((sel & 1) << 2);
    const uint32_t vfl = ((sel & 2) ? AT_SVL : AT_SVH) + (((sel & 1) << 3) + lrow) * AT_P;

    {
        const uint32_t qstb = sb + AT_STW * 4;
#pragma unroll
        for (int i = 0; i < 4; i++) {
            const int c = tid + (i << 8);
            const int row = c >> 3, seg = c & 7;
            const uint32_t w4 = (uint32_t)(row * AT_P + seg * 4) * 4;
            const uint32_t goff = nbase + ((r0 + row) << 5) + (seg << 2);
            cpasync16(qstb + w4, g_qhi32 + goff);
            cpasync16(qstb + AT_SKL * 4 + w4, g_qlo32 + goff);
        }
    }
    CP_COMMIT();
    at_issue(sb, 0, nbase, 0, true, tid);
    CP_COMMIT();
    CP_WAIT(1);
    __syncthreads();

    uint32_t qhf[4][4], qlf[4][4];
    {
        const uint32_t* sQh = sm + AT_STW;
        const uint32_t* sQl = sm + AT_STW + AT_SKL;
#pragma unroll
        for (int kc = 0; kc < 4; kc++) {
            int b0 = (wr + gid) * AT_P + (kc << 3) + tig;
            int b1 = (wr + gid + 8) * AT_P + (kc << 3) + tig;
            qhf[kc][0] = sQh[b0]; qhf[kc][1] = sQh[b1];
            qhf[kc][2] = sQh[b0 + 4]; qhf[kc][3] = sQh[b1 + 4];
            qlf[kc][0] = sQl[b0]; qlf[kc][1] = sQl[b1];
            qlf[kc][2] = sQl[b0 + 4]; qlf[kc][3] = sQl[b1 + 4];
        }
    }
    __syncthreads();

    float m0 = -1e30f, m1 = -1e30f, l0 = 0.f, l1 = 0.f;
    float oacc[8][4];
#pragma unroll
    for (int j = 0; j < 8; j++)
#pragma unroll
        for (int e = 0; e < 4; e++) oacc[j][e] = 0.f;

    const int row0 = r0 + wr + gid, row1 = row0 + 8;

    for (int tb = 0; tb < 8; tb++) {
        const int t0 = tb << 7;
        const bool causal = (tb <= rb);
        if (tb + 1 < 8) {
            at_issue(sb, (tb + 1) & 1, nbase, (tb + 1) << 7, (tb + 1) <= rb, tid);
            CP_COMMIT();
            CP_WAIT(1);
        } else {
            CP_WAIT(0);
        }
        __syncthreads();
        const uint32_t stb = sb + (tb & 1) * (AT_STW * 4);

        // ---- S = Q K^T : kc OUTER / j INNER so consecutive MMAs hit
        // independent accumulators (chain depth 3, not 12). Per-accumulator
        // accumulation order is unchanged -> bit-exact vs previous round.
        float sacc[16][4];
#pragma unroll
        for (int j = 0; j < 16; j++)
#pragma unroll
            for (int e = 0; e < 4; e++) sacc[j][e] = 0.f;
#pragma unroll
        for (int kc = 0; kc < 4; kc++) {
#pragma unroll
            for (int j = 0; j < 16; j++) {
                uint32_t kf[4];
                ldm_x4(kf, stb + (kfl + j * (8 * AT_P) + (kc << 3)) * 4);
                mma16816(sacc[j], qhf[kc], kf);
                mma16816(sacc[j], qlf[kc], kf);
                mma16816(sacc[j], qhf[kc], kf + 2);
            }
        }

        {
            float* h0p = heat + ((size_t)n << 20) + ((size_t)row0 << 10) + t0 + (tig << 1);
            float* h1p = heat + ((size_t)n << 20) + ((size_t)row1 << 10) + t0 + (tig << 1);
#pragma unroll
            for (int j = 0; j < 16; j++) {
                *(float2*)(h0p + (j << 3)) = make_float2(sacc[j][0], sacc[j][1]);
                *(float2*)(h1p + (j << 3)) = make_float2(sacc[j][2], sacc[j][3]);
            }
        }

        if (causal) {
            if (tb == rb) {
#pragma unroll
                for (int j = 0; j < 16; j++) {
                    const int c0 = t0 + (j << 3) + (tig << 1);
                    if (c0 > row0) sacc[j][0] = -1e30f;
                    if (c0 + 1 > row0) sacc[j][1] = -1e30f;
                    if (c0 > row1) sacc[j][2] = -1e30f;
                    if (c0 + 1 > row1) sacc[j][3] = -1e30f;
                }
            }

            float vm0 = -1e30f, vm1 = -1e30f;
#pragma unroll
            for (int j = 0; j < 16; j++) {
                vm0 = fmaxf(vm0, fmaxf(sacc[j][0], sacc[j][1]));
                vm1 = fmaxf(vm1, fmaxf(sacc[j][2], sacc[j][3]));
            }
            vm0 = fmaxf(vm0, __shfl_xor_sync(0xffffffffu, vm0, 1));
            vm0 = fmaxf(vm0, __shfl_xor_sync(0xffffffffu, vm0, 2));
            vm1 = fmaxf(vm1, __shfl_xor_sync(0xffffffffu, vm1, 1));
            vm1 = fmaxf(vm1, __shfl_xor_sync(0xffffffffu, vm1, 2));
            const float mn0 = fmaxf(m0, vm0), mn1 = fmaxf(m1, vm1);
            const float sc0 = __expf(m0 - mn0), sc1 = __expf(m1 - mn1);
            m0 = mn0; m1 = mn1;
            float rs0 = 0.f, rs1 = 0.f;
#pragma unroll
            for (int j = 0; j < 16; j++) {
                sacc[j][0] = __expf(sacc[j][0] - mn0);
                sacc[j][1] = __expf(sacc[j][1] - mn0);
                sacc[j][2] = __expf(sacc[j][2] - mn1);
                sacc[j][3] = __expf(sacc[j][3] - mn1);
                rs0 += sacc[j][0] + sacc[j][1];
                rs1 += sacc[j][2] + sacc[j][3];
            }
            rs0 += __shfl_xor_sync(0xffffffffu, rs0, 1);
            rs0 += __shfl_xor_sync(0xffffffffu, rs0, 2);
            rs1 += __shfl_xor_sync(0xffffffffu, rs1, 1);
            rs1 += __shfl_xor_sync(0xffffffffu, rs1, 2);
            l0 = l0 * sc0 + rs0;
            l1 = l1 * sc1 + rs1;
#pragma unroll
            for (int j = 0; j < 8; j++) {
                oacc[j][0] *= sc0; oacc[j][1] *= sc0;
                oacc[j][2] *= sc1; oacc[j][3] *= sc1;
            }

#pragma unroll
            for (int kt = 0; kt < 8; kt++) {
                uint32_t ph[4], pl[4];
                split2(sacc[2 * kt][0], sacc[2 * kt][1], ph[0], pl[0]);
                split2(sacc[2 * kt][2], sacc[2 * kt][3], ph[1], pl[1]);
                split2(sacc[2 * kt + 1][0], sacc[2 * kt + 1][1], ph[2], pl[2]);
                split2(sacc[2 * kt + 1][2], sacc[2 * kt + 1][3], ph[3], pl[3]);
#pragma unroll
                for (int j = 0; j < 8; j++) {
                    uint32_t vf[4];
                    ldm_x4_t(vf, stb + (vfl + kt * (16 * AT_P) + (j << 2)) * 4);
                    mma16816(oacc[j], ph, vf);
                    mma16816(oacc[j], pl, vf);
                    mma16816(oacc[j], ph, vf + 2);
                }
            }
        }
        __syncthreads();
    }

    const float i0 = 1.0f / l0, i1 = 1.0f / l1;
    const uint32_t wb0 = ((bb << 10) + row0) * 256 + (hh << 5) + tig;
    const uint32_t wb1 = ((bb << 10) + row1) * 256 + (hh << 5) + tig;
#pragma unroll
    for (int j = 0; j < 8; j++) {
        uint32_t hw, lw;
        split2(oacc[j][0] * i0, oacc[j][1] * i0, hw, lw);
        g_wvhi32[wb0 + (j << 2)] = hw;
        g_wvlo32[wb0 + (j << 2)] = lw;
        split2(oacc[j][2] * i1, oacc[j][3] * i1, hw, lw);
        g_wvhi32[wb1 + (j << 2)] = hw;
        g_wvlo32[wb1 + (j << 2)] = lw;
    }
}

// ---------------- launch ------------------------------------------------------
extern "C" void kernel_launch(void* const* d_in, const int* in_sizes, int n_in,
                              void* d_out, int out_size) {
    const float* x  = (const float*)d_in[0];
    const float* Wq = (const float*)d_in[1];
    const float* bq = (const float*)d_in[2];
    const float* Wk = (const float*)d_in[3];
    const float* bk = (const float*)d_in[4];
    const float* Wv = (const float*)d_in[5];
    const float* bv = (const float*)d_in[6];
    const float* Wo = (const float*)d_in[7];
    const float* bo = (const float*)d_in[8];

    float* out = (float*)d_out;
    float* heat = out + (size_t)8 * 1024 * 512;

    cudaFuncSetAttribute(attn_kernel, cudaFuncAttributeMaxDynamicSharedMemorySize,
                         AT_SMEM_BYTES);
    cudaFuncSetAttribute(tgemm, cudaFuncAttributeMaxDynamicSharedMemorySize,
                         TG_SMEM_BYTES);

    conv_x<<<4096, 256>>>(x);
    conv_wt<<<dim3(16, 16, 4), dim3(32, 32)>>>(Wq, Wk, Wv, Wo);

    tgemm<<<dim3(4, 64, 3), 256, TG_SMEM_BYTES>>>(0, 0, bq, bk, bv, nullptr, 1);
    attn_kernel<<<dim3(8, 64), 256, AT_SMEM_BYTES>>>(heat);
    tgemm<<<dim3(4, 64, 1), 256, TG_SMEM_BYTES>>>(1, 3, bo, nullptr, nullptr, out, 0);
}